// round 5
// baseline (speedup 1.0000x reference)
#include <cuda_runtime.h>
#include <cuda_fp16.h>
#include <math.h>
#include <stdint.h>

#define NE 42
#define NM 8
#define LL 1024
#define DD 768
#define HH 12
#define KK 97
#define FF 256
#define RR 256
#define BBS 4
#define NP 512   /* bs * P */

// ---------------- scratch (device globals; no allocs) ----------------
__device__ float g_emb [BBS*NE*NM*DD];
__device__ float g_as  [BBS*NE*HH*LL];
__device__ float g_anT [RR*128];           // attn_net transposed, padded 97->128
__device__ float g_w   [BBS*NE*KK*NM];
__device__ float g_Th  [BBS*NE*NM*DD];
__device__ float g_Tt  [BBS*NE*NM*DD];
__device__ float g_S3  [BBS*LL*3];
__device__ float g_x   [BBS*NE*NE*3];
__device__ float g_htss[NP*FF];
__device__ float g_Rh  [NP*DD];
__device__ float g_Rt  [NP*DD];
__device__ float g_hs  [NP*KK*DD];                     // fp32 head reps (epilogue side)
__device__ __align__(16) __half g_tshi[NP*KK*DD];      // fp16 tail reps
__device__ __align__(16) __half g_Bhi [KK*DD*DD];      // fp16 bilinear weights
__device__ float g_part[6*NP*KK];

__device__ __forceinline__ float ftanh(float x)
{
    float e = __expf(2.0f * x);
    return 1.0f - 2.0f / (e + 1.0f);
}

// ---------------- K1: gather emb + entity_as ----------------
__global__ void k_gather(const float* __restrict__ seq, const float* __restrict__ att,
                         const float* __restrict__ mask, const int* __restrict__ mpos)
{
    int be = blockIdx.x;
    int b  = be / NE;
    int tid = threadIdx.x;
    __shared__ int   spos[NM];
    __shared__ float smk [NM];
    __shared__ float sinv;
    if (tid < NM) {
        int p = mpos[be*NM + tid] + 1;
        p = max(0, min(p, LL-1));
        spos[tid] = p;
        smk[tid]  = mask[be*NM + tid];
    }
    __syncthreads();
    if (tid == 0) {
        float c = 0.f;
        #pragma unroll
        for (int m = 0; m < NM; m++) c += smk[m];
        sinv = 1.0f / fmaxf(c, 1.0f);
    }
    __syncthreads();
    for (int idx = tid; idx < NM*DD; idx += blockDim.x) {
        int m = idx / DD, d = idx - m*DD;
        g_emb[be*NM*DD + idx] = seq[(b*LL + spos[m])*DD + d] * smk[m];
    }
    for (int idx = tid; idx < HH*LL; idx += blockDim.x) {
        int h = idx / LL, l = idx - h*LL;
        float acc = 0.f;
        #pragma unroll
        for (int m = 0; m < NM; m++)
            acc += att[((b*HH + h)*LL + spos[m])*LL + l] * smk[m];
        g_as[be*HH*LL + idx] = acc * sinv;
    }
}

// ---------------- attn_net transpose (97x256 -> 256x128 padded) ----------------
__global__ void k_antr(const float* __restrict__ attn_net)
{
    int idx = blockIdx.x*256 + threadIdx.x;
    if (idx >= RR*128) return;
    int j = idx >> 7, k = idx & 127;
    g_anT[idx] = (k < KK) ? attn_net[k*RR + j] : 0.f;
}

// ---------------- fused mention kernel: t1 = tanh(emb@Wattn+b), scores, softmax ----------------
__global__ __launch_bounds__(256) void k_mention(const float* __restrict__ Wattn,
                                                 const float* __restrict__ battn,
                                                 const float* __restrict__ mask)
{
    int be = blockIdx.x;             // 0..167
    int tid = threadIdx.x;           // 256: one R-column each
    __shared__ float se[NM*DD];      // emb [m][d]  24 KB
    __shared__ float st[RR*9];       // t1 transposed [j][m], pad 9

    const float* eb = g_emb + (size_t)be*NM*DD;
    for (int i = tid; i < NM*DD/4; i += 256)
        *(float4*)&se[i*4] = *(const float4*)&eb[i*4];
    __syncthreads();

    // phase 1: column tid of t1 for all 8 mentions
    float acc[NM];
    float b0 = battn[tid];
    #pragma unroll
    for (int m = 0; m < NM; m++) acc[m] = b0;
    for (int j = 0; j < DD; j += 4) {
        float w0 = Wattn[(j+0)*RR + tid];
        float w1 = Wattn[(j+1)*RR + tid];
        float w2 = Wattn[(j+2)*RR + tid];
        float w3 = Wattn[(j+3)*RR + tid];
        #pragma unroll
        for (int m = 0; m < NM; m++) {
            float4 e = *(const float4*)&se[m*DD + j];
            acc[m] += e.x*w0 + e.y*w1 + e.z*w2 + e.w*w3;
        }
    }
    #pragma unroll
    for (int m = 0; m < NM; m++) st[tid*9 + m] = ftanh(acc[m]);
    __syncthreads();

    // phase 2+3: scores for label tid (<97), softmax over mentions
    if (tid < KK) {
        float sc[NM];
        #pragma unroll
        for (int m = 0; m < NM; m++)
            sc[m] = (1.0f - mask[be*NM + m]) * (-1e6f);
        for (int j = 0; j < RR; j++) {
            float a = g_anT[j*128 + tid];
            float4 t0 = *(const float4*)&st[j*9];
            float4 t1 = *(const float4*)&st[j*9 + 4];
            sc[0] += t0.x*a; sc[1] += t0.y*a; sc[2] += t0.z*a; sc[3] += t0.w*a;
            sc[4] += t1.x*a; sc[5] += t1.y*a; sc[6] += t1.z*a; sc[7] += t1.w*a;
        }
        float mx = sc[0];
        #pragma unroll
        for (int m = 1; m < NM; m++) mx = fmaxf(mx, sc[m]);
        float ssum = 0.f;
        #pragma unroll
        for (int m = 0; m < NM; m++) { sc[m] = expf(sc[m] - mx); ssum += sc[m]; }
        float inv = 1.0f / ssum;
        #pragma unroll
        for (int m = 0; m < NM; m++) g_w[(be*KK + tid)*NM + m] = sc[m]*inv;
    }
}

// ---------------- dual-output SGEMM: two B/C pairs, same A ----------------
__global__ __launch_bounds__(256) void sgemm64_dual(const float* __restrict__ A, int lda,
                                                    const float* __restrict__ B0,
                                                    const float* __restrict__ B1, int ldb,
                                                    const float* __restrict__ bias0,
                                                    const float* __restrict__ bias1,
                                                    float* __restrict__ C0,
                                                    float* __restrict__ C1, int ldc,
                                                    int Kd)
{
    __shared__ float As[16][64];
    __shared__ float Bs[16][68];
    int hx = gridDim.x >> 1;
    int half = blockIdx.x >= hx;
    const float* B    = half ? B1    : B0;
    const float* bias = half ? bias1 : bias0;
    float*       C    = half ? C1    : C0;
    int n0 = (blockIdx.x - half*hx) * 64;
    int m0 = blockIdx.y * 64;
    int tid = threadIdx.x;
    int ty = tid >> 4, tx = tid & 15;
    float acc[4][4];
    #pragma unroll
    for (int i = 0; i < 4; i++)
        #pragma unroll
        for (int j = 0; j < 4; j++) acc[i][j] = 0.f;

    for (int k0 = 0; k0 < Kd; k0 += 16) {
        {
            int r  = tid >> 2;
            int kq = (tid & 3) << 2;
            float4 va = *(const float4*)(A + (long)(m0 + r)*lda + k0 + kq);
            As[kq+0][r] = va.x; As[kq+1][r] = va.y; As[kq+2][r] = va.z; As[kq+3][r] = va.w;
            int kb = tid >> 4;
            int cb = (tid & 15) << 2;
            float4 vb = *(const float4*)(B + (long)(k0 + kb)*ldb + n0 + cb);
            *(float4*)&Bs[kb][cb] = vb;
        }
        __syncthreads();
        #pragma unroll
        for (int kk = 0; kk < 16; kk++) {
            float a[4], bv[4];
            #pragma unroll
            for (int i = 0; i < 4; i++) a[i]  = As[kk][ty*4 + i];
            #pragma unroll
            for (int j = 0; j < 4; j++) bv[j] = Bs[kk][tx*4 + j];
            #pragma unroll
            for (int i = 0; i < 4; i++)
                #pragma unroll
                for (int j = 0; j < 4; j++) acc[i][j] += a[i]*bv[j];
        }
        __syncthreads();
    }
    #pragma unroll
    for (int i = 0; i < 4; i++) {
        int row = m0 + ty*4 + i;
        #pragma unroll
        for (int j = 0; j < 4; j++) {
            int col = n0 + tx*4 + j;
            float v = acc[i][j];
            if (bias) v += bias[col];
            C[(long)row*ldc + col] = v;
        }
    }
}

// ---------------- K6: S3 = seq @ Wlin ----------------
__global__ void k_S3(const float* __restrict__ seq, const float* __restrict__ Wlin)
{
    int row = blockIdx.x;
    int tid = threadIdx.x;
    const float* s = seq + (long)row*DD;
    float a0 = 0.f, a1 = 0.f, a2 = 0.f;
    for (int j = tid; j < DD; j += 128) {
        float v = s[j];
        a0 += v*Wlin[j*3+0]; a1 += v*Wlin[j*3+1]; a2 += v*Wlin[j*3+2];
    }
    __shared__ float red[3][128];
    red[0][tid] = a0; red[1][tid] = a1; red[2][tid] = a2;
    __syncthreads();
    for (int s2 = 64; s2 > 0; s2 >>= 1) {
        if (tid < s2) {
            red[0][tid] += red[0][tid+s2];
            red[1][tid] += red[1][tid+s2];
            red[2][tid] += red[2][tid+s2];
        }
        __syncthreads();
    }
    if (tid < 3) g_S3[row*3 + tid] = red[tid][0];
}

// ---------------- K7: ht + normalization + x = ht@S3 + blin ----------------
__global__ void k_htx(const float* __restrict__ blin)
{
    int b = blockIdx.y;
    int i = blockIdx.x / NE, j = blockIdx.x % NE;
    if (j < i) return;
    int tid = threadIdx.x;
    const float* ai = g_as + (b*NE + i)*HH*LL;
    const float* aj = g_as + (b*NE + j)*HH*LL;
    const float* s3 = g_S3 + b*LL*3;
    float sum = 0.f, x0 = 0.f, x1 = 0.f, x2 = 0.f;
    for (int l = tid; l < LL; l += 256) {
        float acc = 0.f;
        #pragma unroll
        for (int h = 0; h < HH; h++) acc += ai[h*LL + l] * aj[h*LL + l];
        acc *= (1.0f / HH);
        sum += acc;
        x0 += acc * s3[l*3+0];
        x1 += acc * s3[l*3+1];
        x2 += acc * s3[l*3+2];
    }
    __shared__ float red[4][256];
    red[0][tid] = sum; red[1][tid] = x0; red[2][tid] = x1; red[3][tid] = x2;
    __syncthreads();
    for (int s2 = 128; s2 > 0; s2 >>= 1) {
        if (tid < s2) {
            red[0][tid] += red[0][tid+s2];
            red[1][tid] += red[1][tid+s2];
            red[2][tid] += red[2][tid+s2];
            red[3][tid] += red[3][tid+s2];
        }
        __syncthreads();
    }
    if (tid == 0) {
        float inv = 1.0f / (red[0][0] + 1e-5f);
        float v0 = red[1][0]*inv + blin[0];
        float v1 = red[2][0]*inv + blin[1];
        float v2 = red[3][0]*inv + blin[2];
        float* xo = g_x + ((b*NE + i)*NE + j)*3;
        xo[0] = v0; xo[1] = v1; xo[2] = v2;
        float* xm = g_x + ((b*NE + j)*NE + i)*3;
        xm[0] = v0; xm[1] = v1; xm[2] = v2;
    }
}

// ---------------- K8: 3x3 conv + relu at pair positions ----------------
__global__ void k_htss(const int* __restrict__ pairs, const float* __restrict__ Wseg,
                       const float* __restrict__ bseg)
{
    int n = blockIdx.x;
    int b = n >> 7;
    int tid = threadIdx.x;
    __shared__ int shi, sti;
    __shared__ float sx[27];
    if (tid == 0) { shi = pairs[n*2]; sti = pairs[n*2+1]; }
    __syncthreads();
    if (tid < 27) {
        int dy = tid / 9, dx = (tid / 3) % 3, c = tid % 3;
        int ii = shi + dy - 1, jj = sti + dx - 1;
        sx[tid] = (ii >= 0 && ii < NE && jj >= 0 && jj < NE)
                  ? g_x[((b*NE + ii)*NE + jj)*3 + c] : 0.f;
    }
    __syncthreads();
    float acc = bseg[tid];
    #pragma unroll
    for (int t = 0; t < 27; t++) acc += sx[t] * Wseg[t*FF + tid];
    g_htss[n*FF + tid] = fmaxf(acc, 0.f);
}

// ---------------- K10: hs fp32 ; ts -> fp16 ----------------
__global__ __launch_bounds__(256) void k_hsts(const int* __restrict__ pairs)
{
    int n = blockIdx.x;
    int b = n >> 7;
    int tid = threadIdx.x;
    __shared__ float sT[2*NM*DD];
    int hi = pairs[n*2], ti = pairs[n*2+1];
    const float* Th = g_Th + (b*NE + hi)*NM*DD;
    const float* Tt = g_Tt + (b*NE + ti)*NM*DD;
    for (int idx = tid; idx < NM*DD; idx += 256) {
        sT[idx]         = Th[idx];
        sT[NM*DD + idx] = Tt[idx];
    }
    float rh[3], rt[3];
    #pragma unroll
    for (int i2 = 0; i2 < 3; i2++) {
        rh[i2] = g_Rh[n*DD + tid + i2*256];
        rt[i2] = g_Rt[n*DD + tid + i2*256];
    }
    __syncthreads();
    const float* wh = g_w + (b*NE + hi)*KK*NM;
    const float* wt = g_w + (b*NE + ti)*KK*NM;
    for (int k = 0; k < KK; k++) {
        float whr[NM], wtr[NM];
        #pragma unroll
        for (int m = 0; m < NM; m++) {
            whr[m] = __ldg(&wh[k*NM + m]);
            wtr[m] = __ldg(&wt[k*NM + m]);
        }
        #pragma unroll
        for (int i2 = 0; i2 < 3; i2++) {
            int d = tid + i2*256;
            float ah = rh[i2], at2 = rt[i2];
            #pragma unroll
            for (int m = 0; m < NM; m++) {
                ah  += whr[m] * sT[m*DD + d];
                at2 += wtr[m] * sT[NM*DD + m*DD + d];
            }
            size_t o = (size_t)(n*KK + k)*DD + d;
            g_hs[o] = ftanh(ah);
            g_tshi[o] = __float2half_rn(ftanh(at2));
        }
    }
}

// ---------------- K11: bilinear weights -> fp16 ----------------
__global__ void k_bhalf(const float* __restrict__ bil)
{
    size_t i4 = (size_t)blockIdx.x * 256 + threadIdx.x;
    const size_t N4 = (size_t)KK*DD*DD / 4;
    if (i4 >= N4) return;
    float4 v = ((const float4*)bil)[i4];
    __half2* ph = (__half2*)g_Bhi;
    ph[i4*2+0] = __floats2half2_rn(v.x, v.y);
    ph[i4*2+1] = __floats2half2_rn(v.z, v.w);
}

// ================= HMMA (mma.sync fp16) bilinear core, single pass =================
#define SW128(o) ((o) ^ (((o) >> 3) & 0x70))
#define TILE_BYTES 16384                   /* 128 rows x 128B */
#define SH_PITCH 132
#define SMEM_DYN (128*SH_PITCH*4 + 128*2*4 + 1024)

__device__ __forceinline__ void cp16(uint32_t dst, const void* src)
{
    asm volatile("cp.async.cg.shared.global [%0], [%1], 16;" :: "r"(dst), "l"(src));
}
__device__ __forceinline__ void ldm4(uint32_t* r, uint32_t addr)
{
    asm volatile("ldmatrix.sync.aligned.m8n8.x4.shared.b16 {%0,%1,%2,%3}, [%4];"
                 : "=r"(r[0]), "=r"(r[1]), "=r"(r[2]), "=r"(r[3]) : "r"(addr));
}
__device__ __forceinline__ void mma16816(float* c, const uint32_t* a, const uint32_t* b)
{
    asm volatile("mma.sync.aligned.m16n8k16.row.col.f32.f16.f16.f32 "
                 "{%0,%1,%2,%3}, {%4,%5,%6,%7}, {%8,%9}, {%0,%1,%2,%3};"
                 : "+f"(c[0]), "+f"(c[1]), "+f"(c[2]), "+f"(c[3])
                 : "r"(a[0]), "r"(a[1]), "r"(a[2]), "r"(a[3]), "r"(b[0]), "r"(b[1]));
}

__global__ __launch_bounds__(256) void k_bilinear_mma()
{
    extern __shared__ char dsm[];
    char* smem = (char*)((((uintptr_t)dsm) + 1023) & ~(uintptr_t)1023);
    uint32_t sbase = (uint32_t)__cvta_generic_to_shared(smem);

    const int k  = blockIdx.y;
    const int nt = blockIdx.x & 3;
    const int dt = blockIdx.x >> 2;        // 0..5
    const int n0 = nt * 128, d0 = dt * 128;
    const int tid = threadIdx.x;
    const int lane = tid & 31, wid = tid >> 5;
    const int wm = (wid & 3) * 32;         // warp m offset (pairs)
    const int wn = (wid >> 2) * 64;        // warp n offset (d)

    const __half* Abase = g_tshi + ((size_t)n0 * KK + k) * DD;
    const __half* Bbase = g_Bhi + ((size_t)k * DD + d0) * DD;

    float acc[2][8][4];
    #pragma unroll
    for (int mi = 0; mi < 2; mi++)
        #pragma unroll
        for (int ni = 0; ni < 8; ni++)
            #pragma unroll
            for (int j = 0; j < 4; j++) acc[mi][ni][j] = 0.f;

    auto fill = [&](int it, int buf) {
        int k0 = it * 64;
        uint32_t abase = sbase + buf*2*TILE_BYTES;
        uint32_t bbase = abase + TILE_BYTES;
        #pragma unroll
        for (int j = 0; j < 8; j++) {
            int c = tid + j*256;           // 0..2047
            if (c < 1024) {
                int r = c >> 3, q = c & 7;
                cp16(abase + SW128(r*128 + q*16), Abase + (size_t)r*(KK*DD) + k0 + q*8);
            } else {
                int c2 = c - 1024;
                int r = c2 >> 3, q = c2 & 7;
                cp16(bbase + SW128(r*128 + q*16), Bbase + (size_t)r*DD + k0 + q*8);
            }
        }
    };

    fill(0, 0);
    asm volatile("cp.async.commit_group;");

    for (int i = 0; i < 12; i++) {
        if (i + 1 < 12) {
            fill(i + 1, (i + 1) & 1);
            asm volatile("cp.async.commit_group;");
            asm volatile("cp.async.wait_group 1;");
        } else {
            asm volatile("cp.async.wait_group 0;");
        }
        __syncthreads();

        uint32_t abase = sbase + (i & 1)*2*TILE_BYTES;
        uint32_t bbase = abase + TILE_BYTES;
        #pragma unroll
        for (int ks = 0; ks < 4; ks++) {
            uint32_t af[2][4];
            #pragma unroll
            for (int mi = 0; mi < 2; mi++) {
                int row = wm + mi*16 + ((lane >> 3) & 1)*8 + (lane & 7);
                int cb  = ks*32 + (lane >> 4)*16;
                ldm4(af[mi], abase + SW128(row*128 + cb));
            }
            uint32_t bf[8][2];
            #pragma unroll
            for (int q = 0; q < 4; q++) {
                uint32_t r[4];
                int nrow = wn + (2*q + (lane >> 4))*8 + (lane & 7);
                int cb   = ks*32 + ((lane >> 3) & 1)*16;
                ldm4(r, bbase + SW128(nrow*128 + cb));
                bf[2*q+0][0] = r[0]; bf[2*q+0][1] = r[1];
                bf[2*q+1][0] = r[2]; bf[2*q+1][1] = r[3];
            }
            #pragma unroll
            for (int mi = 0; mi < 2; mi++)
                #pragma unroll
                for (int ni = 0; ni < 8; ni++)
                    mma16816(acc[mi][ni], af[mi], bf[ni]);
        }
        __syncthreads();
    }

    // ---- epilogue: partial[n] = sum_d C[n][d]*hs[n][d] ----
    float* sH  = (float*)smem;                     // [128][SH_PITCH]
    float* red = (float*)(smem + 128*SH_PITCH*4);  // [128][2]
    for (int idx = tid; idx < 128*32; idx += 256) {
        int r = idx >> 5, c4 = idx & 31;
        float4 v = *(const float4*)(g_hs + ((size_t)(n0 + r)*KK + k)*DD + d0 + c4*4);
        *(float4*)&sH[r*SH_PITCH + c4*4] = v;
    }
    __syncthreads();

    float p[2][2] = {{0.f, 0.f}, {0.f, 0.f}};
    #pragma unroll
    for (int mi = 0; mi < 2; mi++) {
        int r0 = wm + mi*16 + (lane >> 2);
        #pragma unroll
        for (int ni = 0; ni < 8; ni++) {
            int cb = wn + ni*8 + (lane & 3)*2;
            p[mi][0] += acc[mi][ni][0]*sH[r0*SH_PITCH + cb]
                      + acc[mi][ni][1]*sH[r0*SH_PITCH + cb + 1];
            p[mi][1] += acc[mi][ni][2]*sH[(r0+8)*SH_PITCH + cb]
                      + acc[mi][ni][3]*sH[(r0+8)*SH_PITCH + cb + 1];
        }
    }
    #pragma unroll
    for (int mi = 0; mi < 2; mi++)
        #pragma unroll
        for (int h = 0; h < 2; h++) {
            p[mi][h] += __shfl_xor_sync(0xffffffffu, p[mi][h], 1);
            p[mi][h] += __shfl_xor_sync(0xffffffffu, p[mi][h], 2);
        }
    if ((lane & 3) == 0) {
        int nw = wid >> 2;
        int rr = lane >> 2;
        #pragma unroll
        for (int mi = 0; mi < 2; mi++) {
            red[(wm + mi*16 + rr)*2 + nw]     = p[mi][0];
            red[(wm + mi*16 + rr + 8)*2 + nw] = p[mi][1];
        }
    }
    __syncthreads();
    if (tid < 128)
        g_part[((size_t)dt*NP + n0 + tid)*KK + k] = red[tid*2] + red[tid*2+1];
}

// ---------------- K13: finalize ----------------
__global__ void k_final(const float* __restrict__ bilb, float* __restrict__ out)
{
    int idx = blockIdx.x*256 + threadIdx.x;
    if (idx >= NP*KK) return;
    int k = idx % KK;
    float s = bilb[k];
    #pragma unroll
    for (int t = 0; t < 6; t++) s += g_part[t*(NP*KK) + idx];
    out[idx] = s;
}

// ---------------- launch ----------------
extern "C" void kernel_launch(void* const* d_in, const int* in_sizes, int n_in,
                              void* d_out, int out_size)
{
    const float* seq      = (const float*)d_in[0];
    const float* att      = (const float*)d_in[1];
    const float* mask     = (const float*)d_in[2];
    const int*   mpos     = (const int*)  d_in[3];
    const int*   pairs    = (const int*)  d_in[4];
    const float* Wattn    = (const float*)d_in[5];
    const float* battn    = (const float*)d_in[6];
    const float* attn_net = (const float*)d_in[7];
    const float* Wlin     = (const float*)d_in[8];
    const float* blin     = (const float*)d_in[9];
    const float* Wseg     = (const float*)d_in[10];
    const float* bseg     = (const float*)d_in[11];
    const float* Whead    = (const float*)d_in[12];
    const float* bhead    = (const float*)d_in[13];
    const float* Wtail    = (const float*)d_in[14];
    const float* btail    = (const float*)d_in[15];
    const float* bil      = (const float*)d_in[16];
    const float* bilb     = (const float*)d_in[17];
    float* out = (float*)d_out;

    float *emb, *htss, *Th, *Tt, *Rh, *Rt;
    cudaGetSymbolAddress((void**)&emb,  g_emb);
    cudaGetSymbolAddress((void**)&htss, g_htss);
    cudaGetSymbolAddress((void**)&Th,   g_Th);
    cudaGetSymbolAddress((void**)&Tt,   g_Tt);
    cudaGetSymbolAddress((void**)&Rh,   g_Rh);
    cudaGetSymbolAddress((void**)&Rt,   g_Rt);

    cudaFuncSetAttribute(k_bilinear_mma, cudaFuncAttributeMaxDynamicSharedMemorySize, SMEM_DYN);

    // B weight fp16 convert (independent) first
    {
        size_t n4 = (size_t)KK*DD*DD/4;
        k_bhalf<<<(unsigned)((n4 + 255)/256), 256>>>(bil);
    }
    k_antr<<<(RR*128 + 255)/256, 256>>>(attn_net);
    // 1. gather mention embeddings + entity attention rows
    k_gather<<<BBS*NE, 256>>>(seq, att, mask, mpos);
    // 2+3. fused t1 + scores + softmax
    k_mention<<<BBS*NE, 256>>>(Wattn, battn, mask);
    // 4/5. T_h / T_t merged
    sgemm64_dual<<<dim3(2*(DD/64), (BBS*NE*NM)/64), 256>>>(emb, DD, Whead, Wtail, DD,
                                                           nullptr, nullptr, Th, Tt, DD, DD);
    // 6. S3 = seq @ Wlin
    k_S3<<<BBS*LL, 128>>>(seq, Wlin);
    // 7. ht -> x
    k_htx<<<dim3(NE*NE, BBS), 256>>>(blin);
    // 8. conv + relu at pairs
    k_htss<<<NP, 256>>>(pairs, Wseg, bseg);
    // 9. Rh / Rt merged
    sgemm64_dual<<<dim3(2*(DD/64), NP/64), 256>>>(htss, FF, Whead + DD*DD, Wtail + DD*DD, DD,
                                                  bhead, btail, Rh, Rt, DD, FF);
    // 10. hs fp32 + ts fp16
    k_hsts<<<NP, 256>>>(pairs);
    // 11. HMMA bilinear: grid (24 tiles, 97 k), fp16 single pass
    k_bilinear_mma<<<dim3(24, 97), 256, SMEM_DYN>>>();
    // 12. finalize
    k_final<<<(NP*KK + 255)/256, 256>>>(bilb, out);
}

// round 6
// speedup vs baseline: 1.5101x; 1.5101x over previous
#include <cuda_runtime.h>
#include <cuda_fp16.h>
#include <math.h>
#include <stdint.h>

#define NE 42
#define NM 8
#define LL 1024
#define DD 768
#define HH 12
#define KK 97
#define FF 256
#define RR 256
#define BBS 4
#define NP 512   /* bs * P */

// ---------------- scratch (device globals; no allocs) ----------------
__device__ float g_emb [BBS*NE*NM*DD];
__device__ float g_as  [BBS*NE*HH*LL];
__device__ float g_t1  [BBS*NE*NM*RR];
__device__ float g_anT [RR*128];           // attn_net transposed, padded 97->128
__device__ float g_sc  [BBS*NE*NM*128];    // raw scores [be*m, k]
__device__ float g_w   [BBS*NE*KK*NM];
__device__ float g_Th  [BBS*NE*NM*DD];
__device__ float g_Tt  [BBS*NE*NM*DD];
__device__ float g_S3  [BBS*LL*3];
__device__ float g_x   [BBS*NE*NE*3];
__device__ float g_htss[NP*FF];
__device__ float g_Rh  [NP*DD];
__device__ float g_Rt  [NP*DD];
__device__ __align__(16) __half g_hsh [NP*KK*DD];      // fp16 head reps (epilogue side)
__device__ __align__(16) __half g_tshi[NP*KK*DD];      // fp16 tail reps
__device__ __align__(16) __half g_Bhi [KK*DD*DD];      // fp16 bilinear weights
__device__ float g_part[6*NP*KK];

__device__ __forceinline__ float ftanh(float x)
{
    float e = __expf(2.0f * x);
    return 1.0f - 2.0f / (e + 1.0f);
}

// ---------------- K1: gather emb + entity_as ----------------
__global__ void k_gather(const float* __restrict__ seq, const float* __restrict__ att,
                         const float* __restrict__ mask, const int* __restrict__ mpos)
{
    int be = blockIdx.x;
    int b  = be / NE;
    int tid = threadIdx.x;
    __shared__ int   spos[NM];
    __shared__ float smk [NM];
    __shared__ float sinv;
    if (tid < NM) {
        int p = mpos[be*NM + tid] + 1;
        p = max(0, min(p, LL-1));
        spos[tid] = p;
        smk[tid]  = mask[be*NM + tid];
    }
    __syncthreads();
    if (tid == 0) {
        float c = 0.f;
        #pragma unroll
        for (int m = 0; m < NM; m++) c += smk[m];
        sinv = 1.0f / fmaxf(c, 1.0f);
    }
    __syncthreads();
    for (int idx = tid; idx < NM*DD; idx += blockDim.x) {
        int m = idx / DD, d = idx - m*DD;
        g_emb[be*NM*DD + idx] = seq[(b*LL + spos[m])*DD + d] * smk[m];
    }
    for (int idx = tid; idx < HH*LL; idx += blockDim.x) {
        int h = idx / LL, l = idx - h*LL;
        float acc = 0.f;
        #pragma unroll
        for (int m = 0; m < NM; m++)
            acc += att[((b*HH + h)*LL + spos[m])*LL + l] * smk[m];
        g_as[be*HH*LL + idx] = acc * sinv;
    }
}

// ---------------- generic tiled SGEMM (64x64x16) ----------------
__global__ __launch_bounds__(256) void sgemm64(const float* __restrict__ A, int lda,
                                               const float* __restrict__ B, int ldb,
                                               const float* __restrict__ bias,
                                               float* __restrict__ C, int ldc,
                                               int Kd, int act)
{
    __shared__ float As[16][64];
    __shared__ float Bs[16][68];
    int m0 = blockIdx.y * 64, n0 = blockIdx.x * 64;
    int tid = threadIdx.x;
    int ty = tid >> 4, tx = tid & 15;
    float acc[4][4];
    #pragma unroll
    for (int i = 0; i < 4; i++)
        #pragma unroll
        for (int j = 0; j < 4; j++) acc[i][j] = 0.f;

    for (int k0 = 0; k0 < Kd; k0 += 16) {
        {
            int r  = tid >> 2;
            int kq = (tid & 3) << 2;
            float4 va = *(const float4*)(A + (long)(m0 + r)*lda + k0 + kq);
            As[kq+0][r] = va.x; As[kq+1][r] = va.y; As[kq+2][r] = va.z; As[kq+3][r] = va.w;
            int kb = tid >> 4;
            int cb = (tid & 15) << 2;
            float4 vb = *(const float4*)(B + (long)(k0 + kb)*ldb + n0 + cb);
            *(float4*)&Bs[kb][cb] = vb;
        }
        __syncthreads();
        #pragma unroll
        for (int kk = 0; kk < 16; kk++) {
            float a[4], bv[4];
            #pragma unroll
            for (int i = 0; i < 4; i++) a[i]  = As[kk][ty*4 + i];
            #pragma unroll
            for (int j = 0; j < 4; j++) bv[j] = Bs[kk][tx*4 + j];
            #pragma unroll
            for (int i = 0; i < 4; i++)
                #pragma unroll
                for (int j = 0; j < 4; j++) acc[i][j] += a[i]*bv[j];
        }
        __syncthreads();
    }
    #pragma unroll
    for (int i = 0; i < 4; i++) {
        int row = m0 + ty*4 + i;
        #pragma unroll
        for (int j = 0; j < 4; j++) {
            int col = n0 + tx*4 + j;
            float v = acc[i][j];
            if (bias) v += bias[col];
            if (act)  v = ftanh(v);
            C[(long)row*ldc + col] = v;
        }
    }
}

// ---------------- dual-output SGEMM: two B/C pairs, same A ----------------
__global__ __launch_bounds__(256) void sgemm64_dual(const float* __restrict__ A, int lda,
                                                    const float* __restrict__ B0,
                                                    const float* __restrict__ B1, int ldb,
                                                    const float* __restrict__ bias0,
                                                    const float* __restrict__ bias1,
                                                    float* __restrict__ C0,
                                                    float* __restrict__ C1, int ldc,
                                                    int Kd)
{
    __shared__ float As[16][64];
    __shared__ float Bs[16][68];
    int hx = gridDim.x >> 1;
    int half = blockIdx.x >= hx;
    const float* B    = half ? B1    : B0;
    const float* bias = half ? bias1 : bias0;
    float*       C    = half ? C1    : C0;
    int n0 = (blockIdx.x - half*hx) * 64;
    int m0 = blockIdx.y * 64;
    int tid = threadIdx.x;
    int ty = tid >> 4, tx = tid & 15;
    float acc[4][4];
    #pragma unroll
    for (int i = 0; i < 4; i++)
        #pragma unroll
        for (int j = 0; j < 4; j++) acc[i][j] = 0.f;

    for (int k0 = 0; k0 < Kd; k0 += 16) {
        {
            int r  = tid >> 2;
            int kq = (tid & 3) << 2;
            float4 va = *(const float4*)(A + (long)(m0 + r)*lda + k0 + kq);
            As[kq+0][r] = va.x; As[kq+1][r] = va.y; As[kq+2][r] = va.z; As[kq+3][r] = va.w;
            int kb = tid >> 4;
            int cb = (tid & 15) << 2;
            float4 vb = *(const float4*)(B + (long)(k0 + kb)*ldb + n0 + cb);
            *(float4*)&Bs[kb][cb] = vb;
        }
        __syncthreads();
        #pragma unroll
        for (int kk = 0; kk < 16; kk++) {
            float a[4], bv[4];
            #pragma unroll
            for (int i = 0; i < 4; i++) a[i]  = As[kk][ty*4 + i];
            #pragma unroll
            for (int j = 0; j < 4; j++) bv[j] = Bs[kk][tx*4 + j];
            #pragma unroll
            for (int i = 0; i < 4; i++)
                #pragma unroll
                for (int j = 0; j < 4; j++) acc[i][j] += a[i]*bv[j];
        }
        __syncthreads();
    }
    #pragma unroll
    for (int i = 0; i < 4; i++) {
        int row = m0 + ty*4 + i;
        #pragma unroll
        for (int j = 0; j < 4; j++) {
            int col = n0 + tx*4 + j;
            float v = acc[i][j];
            if (bias) v += bias[col];
            C[(long)row*ldc + col] = v;
        }
    }
}

// ---------------- attn_net transpose (97x256 -> 256x128 padded) ----------------
__global__ void k_antr(const float* __restrict__ attn_net)
{
    int idx = blockIdx.x*256 + threadIdx.x;
    if (idx >= RR*128) return;
    int j = idx >> 7, k = idx & 127;
    g_anT[idx] = (k < KK) ? attn_net[k*RR + j] : 0.f;
}

// ---------------- softmax over mentions ----------------
__global__ void k_softmax(const float* __restrict__ mask)
{
    int be = blockIdx.x;
    int k  = threadIdx.x;            // 128 threads, 97 active
    if (k >= KK) return;
    float neg[NM], sc[NM];
    #pragma unroll
    for (int m = 0; m < NM; m++)
        neg[m] = (1.0f - mask[be*NM + m]) * (-1e6f);
    #pragma unroll
    for (int m = 0; m < NM; m++)
        sc[m] = g_sc[((size_t)(be*NM + m))*128 + k] + neg[m];
    float mx = sc[0];
    #pragma unroll
    for (int m = 1; m < NM; m++) mx = fmaxf(mx, sc[m]);
    float ssum = 0.f;
    #pragma unroll
    for (int m = 0; m < NM; m++) { sc[m] = expf(sc[m] - mx); ssum += sc[m]; }
    float inv = 1.0f / ssum;
    #pragma unroll
    for (int m = 0; m < NM; m++) g_w[(be*KK + k)*NM + m] = sc[m]*inv;
}

// ---------------- K6: S3 = seq @ Wlin ----------------
__global__ void k_S3(const float* __restrict__ seq, const float* __restrict__ Wlin)
{
    int row = blockIdx.x;
    int tid = threadIdx.x;
    const float* s = seq + (long)row*DD;
    float a0 = 0.f, a1 = 0.f, a2 = 0.f;
    for (int j = tid; j < DD; j += 128) {
        float v = s[j];
        a0 += v*Wlin[j*3+0]; a1 += v*Wlin[j*3+1]; a2 += v*Wlin[j*3+2];
    }
    __shared__ float red[3][128];
    red[0][tid] = a0; red[1][tid] = a1; red[2][tid] = a2;
    __syncthreads();
    for (int s2 = 64; s2 > 0; s2 >>= 1) {
        if (tid < s2) {
            red[0][tid] += red[0][tid+s2];
            red[1][tid] += red[1][tid+s2];
            red[2][tid] += red[2][tid+s2];
        }
        __syncthreads();
    }
    if (tid < 3) g_S3[row*3 + tid] = red[tid][0];
}

// ---------------- K7: ht + normalization + x = ht@S3 + blin ----------------
__global__ void k_htx(const float* __restrict__ blin)
{
    int b = blockIdx.y;
    int i = blockIdx.x / NE, j = blockIdx.x % NE;
    if (j < i) return;
    int tid = threadIdx.x;
    const float* ai = g_as + (b*NE + i)*HH*LL;
    const float* aj = g_as + (b*NE + j)*HH*LL;
    const float* s3 = g_S3 + b*LL*3;
    float sum = 0.f, x0 = 0.f, x1 = 0.f, x2 = 0.f;
    for (int l = tid; l < LL; l += 256) {
        float acc = 0.f;
        #pragma unroll
        for (int h = 0; h < HH; h++) acc += ai[h*LL + l] * aj[h*LL + l];
        acc *= (1.0f / HH);
        sum += acc;
        x0 += acc * s3[l*3+0];
        x1 += acc * s3[l*3+1];
        x2 += acc * s3[l*3+2];
    }
    __shared__ float red[4][256];
    red[0][tid] = sum; red[1][tid] = x0; red[2][tid] = x1; red[3][tid] = x2;
    __syncthreads();
    for (int s2 = 128; s2 > 0; s2 >>= 1) {
        if (tid < s2) {
            red[0][tid] += red[0][tid+s2];
            red[1][tid] += red[1][tid+s2];
            red[2][tid] += red[2][tid+s2];
            red[3][tid] += red[3][tid+s2];
        }
        __syncthreads();
    }
    if (tid == 0) {
        float inv = 1.0f / (red[0][0] + 1e-5f);
        float v0 = red[1][0]*inv + blin[0];
        float v1 = red[2][0]*inv + blin[1];
        float v2 = red[3][0]*inv + blin[2];
        float* xo = g_x + ((b*NE + i)*NE + j)*3;
        xo[0] = v0; xo[1] = v1; xo[2] = v2;
        float* xm = g_x + ((b*NE + j)*NE + i)*3;
        xm[0] = v0; xm[1] = v1; xm[2] = v2;
    }
}

// ---------------- K8: 3x3 conv + relu at pair positions ----------------
__global__ void k_htss(const int* __restrict__ pairs, const float* __restrict__ Wseg,
                       const float* __restrict__ bseg)
{
    int n = blockIdx.x;
    int b = n >> 7;
    int tid = threadIdx.x;
    __shared__ int shi, sti;
    __shared__ float sx[27];
    if (tid == 0) { shi = pairs[n*2]; sti = pairs[n*2+1]; }
    __syncthreads();
    if (tid < 27) {
        int dy = tid / 9, dx = (tid / 3) % 3, c = tid % 3;
        int ii = shi + dy - 1, jj = sti + dx - 1;
        sx[tid] = (ii >= 0 && ii < NE && jj >= 0 && jj < NE)
                  ? g_x[((b*NE + ii)*NE + jj)*3 + c] : 0.f;
    }
    __syncthreads();
    float acc = bseg[tid];
    #pragma unroll
    for (int t = 0; t < 27; t++) acc += sx[t] * Wseg[t*FF + tid];
    g_htss[n*FF + tid] = fmaxf(acc, 0.f);
}

// ---------------- K10: hs,ts -> fp16 ----------------
__global__ __launch_bounds__(256) void k_hsts(const int* __restrict__ pairs)
{
    int n = blockIdx.x;
    int b = n >> 7;
    int tid = threadIdx.x;
    __shared__ float sT[2*NM*DD];
    int hi = pairs[n*2], ti = pairs[n*2+1];
    const float* Th = g_Th + (b*NE + hi)*NM*DD;
    const float* Tt = g_Tt + (b*NE + ti)*NM*DD;
    for (int idx = tid; idx < NM*DD; idx += 256) {
        sT[idx]         = Th[idx];
        sT[NM*DD + idx] = Tt[idx];
    }
    float rh[3], rt[3];
    #pragma unroll
    for (int i2 = 0; i2 < 3; i2++) {
        rh[i2] = g_Rh[n*DD + tid + i2*256];
        rt[i2] = g_Rt[n*DD + tid + i2*256];
    }
    __syncthreads();
    const float* wh = g_w + (b*NE + hi)*KK*NM;
    const float* wt = g_w + (b*NE + ti)*KK*NM;
    for (int k = 0; k < KK; k++) {
        float whr[NM], wtr[NM];
        #pragma unroll
        for (int m = 0; m < NM; m++) {
            whr[m] = __ldg(&wh[k*NM + m]);
            wtr[m] = __ldg(&wt[k*NM + m]);
        }
        #pragma unroll
        for (int i2 = 0; i2 < 3; i2++) {
            int d = tid + i2*256;
            float ah = rh[i2], at2 = rt[i2];
            #pragma unroll
            for (int m = 0; m < NM; m++) {
                ah  += whr[m] * sT[m*DD + d];
                at2 += wtr[m] * sT[NM*DD + m*DD + d];
            }
            size_t o = (size_t)(n*KK + k)*DD + d;
            g_hsh[o]  = __float2half_rn(ftanh(ah));
            g_tshi[o] = __float2half_rn(ftanh(at2));
        }
    }
}

// ---------------- K11: bilinear weights -> fp16 ----------------
__global__ void k_bhalf(const float* __restrict__ bil)
{
    size_t i4 = (size_t)blockIdx.x * 256 + threadIdx.x;
    const size_t N4 = (size_t)KK*DD*DD / 4;
    if (i4 >= N4) return;
    float4 v = ((const float4*)bil)[i4];
    __half2* ph = (__half2*)g_Bhi;
    ph[i4*2+0] = __floats2half2_rn(v.x, v.y);
    ph[i4*2+1] = __floats2half2_rn(v.z, v.w);
}

// ================= HMMA (mma.sync fp16) bilinear core, single pass =================
#define SW128(o) ((o) ^ (((o) >> 3) & 0x70))
#define TILE_BYTES 16384                   /* 128 rows x 128B */
#define SH_PITCH 132
#define SMEM_DYN (128*SH_PITCH*4 + 128*2*4 + 1024)

__device__ __forceinline__ void cp16(uint32_t dst, const void* src)
{
    asm volatile("cp.async.cg.shared.global [%0], [%1], 16;" :: "r"(dst), "l"(src));
}
__device__ __forceinline__ void ldm4(uint32_t* r, uint32_t addr)
{
    asm volatile("ldmatrix.sync.aligned.m8n8.x4.shared.b16 {%0,%1,%2,%3}, [%4];"
                 : "=r"(r[0]), "=r"(r[1]), "=r"(r[2]), "=r"(r[3]) : "r"(addr));
}
__device__ __forceinline__ void mma16816(float* c, const uint32_t* a, const uint32_t* b)
{
    asm volatile("mma.sync.aligned.m16n8k16.row.col.f32.f16.f16.f32 "
                 "{%0,%1,%2,%3}, {%4,%5,%6,%7}, {%8,%9}, {%0,%1,%2,%3};"
                 : "+f"(c[0]), "+f"(c[1]), "+f"(c[2]), "+f"(c[3])
                 : "r"(a[0]), "r"(a[1]), "r"(a[2]), "r"(a[3]), "r"(b[0]), "r"(b[1]));
}

__global__ __launch_bounds__(256) void k_bilinear_mma()
{
    extern __shared__ char dsm[];
    char* smem = (char*)((((uintptr_t)dsm) + 1023) & ~(uintptr_t)1023);
    uint32_t sbase = (uint32_t)__cvta_generic_to_shared(smem);

    const int k  = blockIdx.y;
    const int nt = blockIdx.x & 3;
    const int dt = blockIdx.x >> 2;        // 0..5
    const int n0 = nt * 128, d0 = dt * 128;
    const int tid = threadIdx.x;
    const int lane = tid & 31, wid = tid >> 5;
    const int wm = (wid & 3) * 32;         // warp m offset (pairs)
    const int wn = (wid >> 2) * 64;        // warp n offset (d)

    const __half* Abase = g_tshi + ((size_t)n0 * KK + k) * DD;
    const __half* Bbase = g_Bhi + ((size_t)k * DD + d0) * DD;

    float acc[2][8][4];
    #pragma unroll
    for (int mi = 0; mi < 2; mi++)
        #pragma unroll
        for (int ni = 0; ni < 8; ni++)
            #pragma unroll
            for (int j = 0; j < 4; j++) acc[mi][ni][j] = 0.f;

    auto fill = [&](int it, int buf) {
        int k0 = it * 64;
        uint32_t abase = sbase + buf*2*TILE_BYTES;
        uint32_t bbase = abase + TILE_BYTES;
        #pragma unroll
        for (int j = 0; j < 8; j++) {
            int c = tid + j*256;           // 0..2047
            if (c < 1024) {
                int r = c >> 3, q = c & 7;
                cp16(abase + SW128(r*128 + q*16), Abase + (size_t)r*(KK*DD) + k0 + q*8);
            } else {
                int c2 = c - 1024;
                int r = c2 >> 3, q = c2 & 7;
                cp16(bbase + SW128(r*128 + q*16), Bbase + (size_t)r*DD + k0 + q*8);
            }
        }
    };

    fill(0, 0);
    asm volatile("cp.async.commit_group;");

    for (int i = 0; i < 12; i++) {
        if (i + 1 < 12) {
            fill(i + 1, (i + 1) & 1);
            asm volatile("cp.async.commit_group;");
            asm volatile("cp.async.wait_group 1;");
        } else {
            asm volatile("cp.async.wait_group 0;");
        }
        __syncthreads();

        uint32_t abase = sbase + (i & 1)*2*TILE_BYTES;
        uint32_t bbase = abase + TILE_BYTES;
        #pragma unroll
        for (int ks = 0; ks < 4; ks++) {
            uint32_t af[2][4];
            #pragma unroll
            for (int mi = 0; mi < 2; mi++) {
                int row = wm + mi*16 + ((lane >> 3) & 1)*8 + (lane & 7);
                int cb  = ks*32 + (lane >> 4)*16;
                ldm4(af[mi], abase + SW128(row*128 + cb));
            }
            uint32_t bf[8][2];
            #pragma unroll
            for (int q = 0; q < 4; q++) {
                uint32_t r[4];
                int nrow = wn + (2*q + (lane >> 4))*8 + (lane & 7);
                int cb   = ks*32 + ((lane >> 3) & 1)*16;
                ldm4(r, bbase + SW128(nrow*128 + cb));
                bf[2*q+0][0] = r[0]; bf[2*q+0][1] = r[1];
                bf[2*q+1][0] = r[2]; bf[2*q+1][1] = r[3];
            }
            #pragma unroll
            for (int mi = 0; mi < 2; mi++)
                #pragma unroll
                for (int ni = 0; ni < 8; ni++)
                    mma16816(acc[mi][ni], af[mi], bf[ni]);
        }
        __syncthreads();
    }

    // ---- epilogue: partial[n] = sum_d C[n][d]*hs[n][d] (hs fp16 in gmem) ----
    float* sH  = (float*)smem;                     // [128][SH_PITCH]
    float* red = (float*)(smem + 128*SH_PITCH*4);  // [128][2]
    for (int idx = tid; idx < 128*16; idx += 256) {
        int r = idx >> 4, c8 = idx & 15;           // 8 halves per chunk
        const __half2* hp = (const __half2*)(g_hsh + ((size_t)(n0 + r)*KK + k)*DD + d0 + c8*8);
        float* dst = &sH[r*SH_PITCH + c8*8];
        #pragma unroll
        for (int u = 0; u < 4; u++) {
            float2 f = __half22float2(hp[u]);
            dst[u*2+0] = f.x; dst[u*2+1] = f.y;
        }
    }
    __syncthreads();

    float p[2][2] = {{0.f, 0.f}, {0.f, 0.f}};
    #pragma unroll
    for (int mi = 0; mi < 2; mi++) {
        int r0 = wm + mi*16 + (lane >> 2);
        #pragma unroll
        for (int ni = 0; ni < 8; ni++) {
            int cb = wn + ni*8 + (lane & 3)*2;
            p[mi][0] += acc[mi][ni][0]*sH[r0*SH_PITCH + cb]
                      + acc[mi][ni][1]*sH[r0*SH_PITCH + cb + 1];
            p[mi][1] += acc[mi][ni][2]*sH[(r0+8)*SH_PITCH + cb]
                      + acc[mi][ni][3]*sH[(r0+8)*SH_PITCH + cb + 1];
        }
    }
    #pragma unroll
    for (int mi = 0; mi < 2; mi++)
        #pragma unroll
        for (int h = 0; h < 2; h++) {
            p[mi][h] += __shfl_xor_sync(0xffffffffu, p[mi][h], 1);
            p[mi][h] += __shfl_xor_sync(0xffffffffu, p[mi][h], 2);
        }
    if ((lane & 3) == 0) {
        int nw = wid >> 2;
        int rr = lane >> 2;
        #pragma unroll
        for (int mi = 0; mi < 2; mi++) {
            red[(wm + mi*16 + rr)*2 + nw]     = p[mi][0];
            red[(wm + mi*16 + rr + 8)*2 + nw] = p[mi][1];
        }
    }
    __syncthreads();
    if (tid < 128)
        g_part[((size_t)dt*NP + n0 + tid)*KK + k] = red[tid*2] + red[tid*2+1];
}

// ---------------- K13: finalize ----------------
__global__ void k_final(const float* __restrict__ bilb, float* __restrict__ out)
{
    int idx = blockIdx.x*256 + threadIdx.x;
    if (idx >= NP*KK) return;
    int k = idx % KK;
    float s = bilb[k];
    #pragma unroll
    for (int t = 0; t < 6; t++) s += g_part[t*(NP*KK) + idx];
    out[idx] = s;
}

// ---------------- launch ----------------
extern "C" void kernel_launch(void* const* d_in, const int* in_sizes, int n_in,
                              void* d_out, int out_size)
{
    const float* seq      = (const float*)d_in[0];
    const float* att      = (const float*)d_in[1];
    const float* mask     = (const float*)d_in[2];
    const int*   mpos     = (const int*)  d_in[3];
    const int*   pairs    = (const int*)  d_in[4];
    const float* Wattn    = (const float*)d_in[5];
    const float* battn    = (const float*)d_in[6];
    const float* attn_net = (const float*)d_in[7];
    const float* Wlin     = (const float*)d_in[8];
    const float* blin     = (const float*)d_in[9];
    const float* Wseg     = (const float*)d_in[10];
    const float* bseg     = (const float*)d_in[11];
    const float* Whead    = (const float*)d_in[12];
    const float* bhead    = (const float*)d_in[13];
    const float* Wtail    = (const float*)d_in[14];
    const float* btail    = (const float*)d_in[15];
    const float* bil      = (const float*)d_in[16];
    const float* bilb     = (const float*)d_in[17];
    float* out = (float*)d_out;

    float *emb, *t1, *anT, *sc, *htss, *Th, *Tt, *Rh, *Rt;
    cudaGetSymbolAddress((void**)&emb,  g_emb);
    cudaGetSymbolAddress((void**)&t1,   g_t1);
    cudaGetSymbolAddress((void**)&anT,  g_anT);
    cudaGetSymbolAddress((void**)&sc,   g_sc);
    cudaGetSymbolAddress((void**)&htss, g_htss);
    cudaGetSymbolAddress((void**)&Th,   g_Th);
    cudaGetSymbolAddress((void**)&Tt,   g_Tt);
    cudaGetSymbolAddress((void**)&Rh,   g_Rh);
    cudaGetSymbolAddress((void**)&Rt,   g_Rt);

    cudaFuncSetAttribute(k_bilinear_mma, cudaFuncAttributeMaxDynamicSharedMemorySize, SMEM_DYN);

    // B weight fp16 convert (independent) first
    {
        size_t n4 = (size_t)KK*DD*DD/4;
        k_bhalf<<<(unsigned)((n4 + 255)/256), 256>>>(bil);
    }
    k_antr<<<(RR*128 + 255)/256, 256>>>(attn_net);
    // 1. gather mention embeddings + entity attention rows
    k_gather<<<BBS*NE, 256>>>(seq, att, mask, mpos);
    // 2. t1 = tanh(emb @ Wattn + battn)
    sgemm64<<<dim3(RR/64, (BBS*NE*NM)/64), 256>>>(emb, DD, Wattn, RR, battn, t1, RR, DD, 1);
    // 3. scores = t1 @ anT  -> softmax over mentions
    sgemm64<<<dim3(2, (BBS*NE*NM)/64), 256>>>(t1, RR, anT, 128, nullptr, sc, 128, RR, 0);
    k_softmax<<<BBS*NE, 128>>>(mask);
    // 4/5. T_h / T_t merged
    sgemm64_dual<<<dim3(2*(DD/64), (BBS*NE*NM)/64), 256>>>(emb, DD, Whead, Wtail, DD,
                                                           nullptr, nullptr, Th, Tt, DD, DD);
    // 6. S3 = seq @ Wlin
    k_S3<<<BBS*LL, 128>>>(seq, Wlin);
    // 7. ht -> x
    k_htx<<<dim3(NE*NE, BBS), 256>>>(blin);
    // 8. conv + relu at pairs
    k_htss<<<NP, 256>>>(pairs, Wseg, bseg);
    // 9. Rh / Rt merged
    sgemm64_dual<<<dim3(2*(DD/64), NP/64), 256>>>(htss, FF, Whead + DD*DD, Wtail + DD*DD, DD,
                                                  bhead, btail, Rh, Rt, DD, FF);
    // 10. hs,ts fp16
    k_hsts<<<NP, 256>>>(pairs);
    // 11. HMMA bilinear: grid (24 tiles, 97 k), fp16 single pass
    k_bilinear_mma<<<dim3(24, 97), 256, SMEM_DYN>>>();
    // 12. finalize
    k_final<<<(NP*KK + 255)/256, 256>>>(bilb, out);
}

// round 7
// speedup vs baseline: 1.6147x; 1.0693x over previous
#include <cuda_runtime.h>
#include <cuda_fp16.h>
#include <math.h>
#include <stdint.h>

#define NE 42
#define NM 8
#define LL 1024
#define DD 768
#define HH 12
#define KK 97
#define FF 256
#define RR 256
#define BBS 4
#define NP 512   /* bs * P */

// ---------------- scratch (device globals; no allocs) ----------------
__device__ float g_emb [BBS*NE*NM*DD];
__device__ float g_as  [BBS*NE*HH*LL];
__device__ float g_t1  [BBS*NE*NM*RR];
__device__ float g_anT [RR*128];           // attn_net transposed, padded 97->128
__device__ float g_w   [BBS*NE*KK*NM];
__device__ float g_Th  [BBS*NE*NM*DD];
__device__ float g_Tt  [BBS*NE*NM*DD];
__device__ float g_S3  [BBS*LL*3];
__device__ float g_x   [BBS*NE*NE*3];
__device__ float g_htss[NP*FF];
__device__ float g_Rh  [NP*DD];
__device__ float g_Rt  [NP*DD];
__device__ __align__(16) __half g_hsh [NP*KK*DD];      // fp16 head reps (epilogue side)
__device__ __align__(16) __half g_tshi[NP*KK*DD];      // fp16 tail reps
__device__ __align__(16) __half g_Bhi [KK*DD*DD];      // fp16 bilinear weights
__device__ float g_part[6*NP*KK];

__device__ __forceinline__ float ftanh(float x)
{
    float e = __expf(2.0f * x);
    return 1.0f - 2.0f / (e + 1.0f);
}

__device__ __forceinline__ void cp16(uint32_t dst, const void* src)
{
    asm volatile("cp.async.cg.shared.global [%0], [%1], 16;" :: "r"(dst), "l"(src));
}

// ---------------- K1: gather emb + entity_as ----------------
__global__ void k_gather(const float* __restrict__ seq, const float* __restrict__ att,
                         const float* __restrict__ mask, const int* __restrict__ mpos)
{
    int be = blockIdx.x;
    int b  = be / NE;
    int tid = threadIdx.x;
    __shared__ int   spos[NM];
    __shared__ float smk [NM];
    __shared__ float sinv;
    if (tid < NM) {
        int p = mpos[be*NM + tid] + 1;
        p = max(0, min(p, LL-1));
        spos[tid] = p;
        smk[tid]  = mask[be*NM + tid];
    }
    __syncthreads();
    if (tid == 0) {
        float c = 0.f;
        #pragma unroll
        for (int m = 0; m < NM; m++) c += smk[m];
        sinv = 1.0f / fmaxf(c, 1.0f);
    }
    __syncthreads();
    for (int idx = tid; idx < NM*DD; idx += blockDim.x) {
        int m = idx / DD, d = idx - m*DD;
        g_emb[be*NM*DD + idx] = seq[(b*LL + spos[m])*DD + d] * smk[m];
    }
    for (int idx = tid; idx < HH*LL; idx += blockDim.x) {
        int h = idx / LL, l = idx - h*LL;
        float acc = 0.f;
        #pragma unroll
        for (int m = 0; m < NM; m++)
            acc += att[((b*HH + h)*LL + spos[m])*LL + l] * smk[m];
        g_as[be*HH*LL + idx] = acc * sinv;
    }
}

// ---------------- cp.async double-buffered SGEMM (64x64x32) ----------------
__global__ __launch_bounds__(256) void sgemm_ca(const float* __restrict__ A, int lda,
                                                const float* __restrict__ B, int ldb,
                                                const float* __restrict__ bias,
                                                float* __restrict__ C, int ldc,
                                                int Kd, int act)
{
    __shared__ float As[2][64][32];
    __shared__ float Bs[2][32][68];
    int m0 = blockIdx.y * 64, n0 = blockIdx.x * 64;
    int tid = threadIdx.x;
    int ty = tid >> 4, tx = tid & 15;
    uint32_t sA = (uint32_t)__cvta_generic_to_shared(&As[0][0][0]);
    uint32_t sB = (uint32_t)__cvta_generic_to_shared(&Bs[0][0][0]);
    float acc[4][4];
    #pragma unroll
    for (int i = 0; i < 4; i++)
        #pragma unroll
        for (int j = 0; j < 4; j++) acc[i][j] = 0.f;

    int nstage = Kd >> 5;
    auto fill = [&](int s, int k0) {
        #pragma unroll
        for (int j = 0; j < 2; j++) {
            int c = tid + j*256;
            int r = c >> 3, q = c & 7;            // A: row r, 16B col q
            cp16(sA + (uint32_t)(s*64*32 + r*32 + q*4)*4,
                 A + (size_t)(m0 + r)*lda + k0 + q*4);
            int rb = c >> 4, qb = c & 15;         // B: k-row rb, 16B col qb
            cp16(sB + (uint32_t)(s*32*68 + rb*68 + qb*4)*4,
                 B + (size_t)(k0 + rb)*ldb + n0 + qb*4);
        }
        asm volatile("cp.async.commit_group;");
    };

    fill(0, 0);
    for (int s = 0; s < nstage; s++) {
        if (s + 1 < nstage) {
            fill((s + 1) & 1, (s + 1) << 5);
            asm volatile("cp.async.wait_group 1;");
        } else {
            asm volatile("cp.async.wait_group 0;");
        }
        __syncthreads();
        int bs = s & 1;
        #pragma unroll
        for (int kk = 0; kk < 32; kk++) {
            float a[4], bv[4];
            #pragma unroll
            for (int i = 0; i < 4; i++) a[i]  = As[bs][ty*4 + i][kk];
            #pragma unroll
            for (int j = 0; j < 4; j++) bv[j] = Bs[bs][kk][tx*4 + j];
            #pragma unroll
            for (int i = 0; i < 4; i++)
                #pragma unroll
                for (int j = 0; j < 4; j++) acc[i][j] += a[i]*bv[j];
        }
        __syncthreads();
    }
    #pragma unroll
    for (int i = 0; i < 4; i++) {
        int row = m0 + ty*4 + i;
        #pragma unroll
        for (int j = 0; j < 4; j++) {
            int col = n0 + tx*4 + j;
            float v = acc[i][j];
            if (bias) v += bias[col];
            if (act)  v = ftanh(v);
            C[(size_t)row*ldc + col] = v;
        }
    }
}

// ---------------- dual-output cp.async SGEMM ----------------
__global__ __launch_bounds__(256) void sgemm_ca_dual(const float* __restrict__ A, int lda,
                                                     const float* __restrict__ B0,
                                                     const float* __restrict__ B1, int ldb,
                                                     const float* __restrict__ bias0,
                                                     const float* __restrict__ bias1,
                                                     float* __restrict__ C0,
                                                     float* __restrict__ C1, int ldc,
                                                     int Kd)
{
    __shared__ float As[2][64][32];
    __shared__ float Bs[2][32][68];
    int hx = gridDim.x >> 1;
    int half = blockIdx.x >= hx;
    const float* B    = half ? B1    : B0;
    const float* bias = half ? bias1 : bias0;
    float*       C    = half ? C1    : C0;
    int n0 = (blockIdx.x - half*hx) * 64;
    int m0 = blockIdx.y * 64;
    int tid = threadIdx.x;
    int ty = tid >> 4, tx = tid & 15;
    uint32_t sA = (uint32_t)__cvta_generic_to_shared(&As[0][0][0]);
    uint32_t sB = (uint32_t)__cvta_generic_to_shared(&Bs[0][0][0]);
    float acc[4][4];
    #pragma unroll
    for (int i = 0; i < 4; i++)
        #pragma unroll
        for (int j = 0; j < 4; j++) acc[i][j] = 0.f;

    int nstage = Kd >> 5;
    auto fill = [&](int s, int k0) {
        #pragma unroll
        for (int j = 0; j < 2; j++) {
            int c = tid + j*256;
            int r = c >> 3, q = c & 7;
            cp16(sA + (uint32_t)(s*64*32 + r*32 + q*4)*4,
                 A + (size_t)(m0 + r)*lda + k0 + q*4);
            int rb = c >> 4, qb = c & 15;
            cp16(sB + (uint32_t)(s*32*68 + rb*68 + qb*4)*4,
                 B + (size_t)(k0 + rb)*ldb + n0 + qb*4);
        }
        asm volatile("cp.async.commit_group;");
    };

    fill(0, 0);
    for (int s = 0; s < nstage; s++) {
        if (s + 1 < nstage) {
            fill((s + 1) & 1, (s + 1) << 5);
            asm volatile("cp.async.wait_group 1;");
        } else {
            asm volatile("cp.async.wait_group 0;");
        }
        __syncthreads();
        int bs = s & 1;
        #pragma unroll
        for (int kk = 0; kk < 32; kk++) {
            float a[4], bv[4];
            #pragma unroll
            for (int i = 0; i < 4; i++) a[i]  = As[bs][ty*4 + i][kk];
            #pragma unroll
            for (int j = 0; j < 4; j++) bv[j] = Bs[bs][kk][tx*4 + j];
            #pragma unroll
            for (int i = 0; i < 4; i++)
                #pragma unroll
                for (int j = 0; j < 4; j++) acc[i][j] += a[i]*bv[j];
        }
        __syncthreads();
    }
    #pragma unroll
    for (int i = 0; i < 4; i++) {
        int row = m0 + ty*4 + i;
        #pragma unroll
        for (int j = 0; j < 4; j++) {
            int col = n0 + tx*4 + j;
            float v = acc[i][j];
            if (bias) v += bias[col];
            C[(size_t)row*ldc + col] = v;
        }
    }
}

// ---------------- attn_net transpose (97x256 -> 256x128 padded) ----------------
__global__ void k_antr(const float* __restrict__ attn_net)
{
    int idx = blockIdx.x*256 + threadIdx.x;
    if (idx >= RR*128) return;
    int j = idx >> 7, k = idx & 127;
    g_anT[idx] = (k < KK) ? attn_net[k*RR + j] : 0.f;
}

// ---------------- fused scores + softmax over mentions ----------------
__global__ __launch_bounds__(128) void k_scsm(const float* __restrict__ mask)
{
    int be = blockIdx.x;
    int tid = threadIdx.x;           // 128
    __shared__ float st[NM*RR];      // t1 rows for this entity, [m][j]
    for (int i = tid; i < NM*RR/4; i += 128)
        *(float4*)&st[i*4] = *(const float4*)&g_t1[(size_t)be*NM*RR + i*4];
    __syncthreads();
    if (tid >= KK) return;
    float sc[NM];
    #pragma unroll
    for (int m = 0; m < NM; m++)
        sc[m] = (1.0f - mask[be*NM + m]) * (-1e6f);
    for (int j = 0; j < RR; j++) {
        float a = g_anT[j*128 + tid];
        #pragma unroll
        for (int m = 0; m < NM; m++) sc[m] += st[m*RR + j] * a;
    }
    float mx = sc[0];
    #pragma unroll
    for (int m = 1; m < NM; m++) mx = fmaxf(mx, sc[m]);
    float ssum = 0.f;
    #pragma unroll
    for (int m = 0; m < NM; m++) { sc[m] = expf(sc[m] - mx); ssum += sc[m]; }
    float inv = 1.0f / ssum;
    #pragma unroll
    for (int m = 0; m < NM; m++) g_w[(be*KK + tid)*NM + m] = sc[m]*inv;
}

// ---------------- K6: S3 = seq @ Wlin ----------------
__global__ void k_S3(const float* __restrict__ seq, const float* __restrict__ Wlin)
{
    int row = blockIdx.x;
    int tid = threadIdx.x;
    const float* s = seq + (size_t)row*DD;
    float a0 = 0.f, a1 = 0.f, a2 = 0.f;
    for (int j = tid; j < DD; j += 128) {
        float v = s[j];
        a0 += v*Wlin[j*3+0]; a1 += v*Wlin[j*3+1]; a2 += v*Wlin[j*3+2];
    }
    __shared__ float red[3][128];
    red[0][tid] = a0; red[1][tid] = a1; red[2][tid] = a2;
    __syncthreads();
    for (int s2 = 64; s2 > 0; s2 >>= 1) {
        if (tid < s2) {
            red[0][tid] += red[0][tid+s2];
            red[1][tid] += red[1][tid+s2];
            red[2][tid] += red[2][tid+s2];
        }
        __syncthreads();
    }
    if (tid < 3) g_S3[row*3 + tid] = red[tid][0];
}

// ---------------- K7: ht + normalization + x = ht@S3 + blin ----------------
__global__ void k_htx(const float* __restrict__ blin)
{
    int b = blockIdx.y;
    int i = blockIdx.x / NE, j = blockIdx.x % NE;
    if (j < i) return;
    int tid = threadIdx.x;
    const float* ai = g_as + (b*NE + i)*HH*LL;
    const float* aj = g_as + (b*NE + j)*HH*LL;
    const float* s3 = g_S3 + b*LL*3;
    float sum = 0.f, x0 = 0.f, x1 = 0.f, x2 = 0.f;
    for (int l = tid; l < LL; l += 256) {
        float acc = 0.f;
        #pragma unroll
        for (int h = 0; h < HH; h++) acc += ai[h*LL + l] * aj[h*LL + l];
        acc *= (1.0f / HH);
        sum += acc;
        x0 += acc * s3[l*3+0];
        x1 += acc * s3[l*3+1];
        x2 += acc * s3[l*3+2];
    }
    __shared__ float red[4][256];
    red[0][tid] = sum; red[1][tid] = x0; red[2][tid] = x1; red[3][tid] = x2;
    __syncthreads();
    for (int s2 = 128; s2 > 0; s2 >>= 1) {
        if (tid < s2) {
            red[0][tid] += red[0][tid+s2];
            red[1][tid] += red[1][tid+s2];
            red[2][tid] += red[2][tid+s2];
            red[3][tid] += red[3][tid+s2];
        }
        __syncthreads();
    }
    if (tid == 0) {
        float inv = 1.0f / (red[0][0] + 1e-5f);
        float v0 = red[1][0]*inv + blin[0];
        float v1 = red[2][0]*inv + blin[1];
        float v2 = red[3][0]*inv + blin[2];
        float* xo = g_x + ((b*NE + i)*NE + j)*3;
        xo[0] = v0; xo[1] = v1; xo[2] = v2;
        float* xm = g_x + ((b*NE + j)*NE + i)*3;
        xm[0] = v0; xm[1] = v1; xm[2] = v2;
    }
}

// ---------------- K8: 3x3 conv + relu at pair positions ----------------
__global__ void k_htss(const int* __restrict__ pairs, const float* __restrict__ Wseg,
                       const float* __restrict__ bseg)
{
    int n = blockIdx.x;
    int b = n >> 7;
    int tid = threadIdx.x;
    __shared__ int shi, sti;
    __shared__ float sx[27];
    if (tid == 0) { shi = pairs[n*2]; sti = pairs[n*2+1]; }
    __syncthreads();
    if (tid < 27) {
        int dy = tid / 9, dx = (tid / 3) % 3, c = tid % 3;
        int ii = shi + dy - 1, jj = sti + dx - 1;
        sx[tid] = (ii >= 0 && ii < NE && jj >= 0 && jj < NE)
                  ? g_x[((b*NE + ii)*NE + jj)*3 + c] : 0.f;
    }
    __syncthreads();
    float acc = bseg[tid];
    #pragma unroll
    for (int t = 0; t < 27; t++) acc += sx[t] * Wseg[t*FF + tid];
    g_htss[n*FF + tid] = fmaxf(acc, 0.f);
}

// ---------------- K10: hs,ts -> fp16 ----------------
__global__ __launch_bounds__(256) void k_hsts(const int* __restrict__ pairs)
{
    int n = blockIdx.x;
    int b = n >> 7;
    int tid = threadIdx.x;
    __shared__ float sT[2*NM*DD];
    int hi = pairs[n*2], ti = pairs[n*2+1];
    const float* Th = g_Th + (b*NE + hi)*NM*DD;
    const float* Tt = g_Tt + (b*NE + ti)*NM*DD;
    for (int idx = tid; idx < NM*DD; idx += 256) {
        sT[idx]         = Th[idx];
        sT[NM*DD + idx] = Tt[idx];
    }
    float rh[3], rt[3];
    #pragma unroll
    for (int i2 = 0; i2 < 3; i2++) {
        rh[i2] = g_Rh[n*DD + tid + i2*256];
        rt[i2] = g_Rt[n*DD + tid + i2*256];
    }
    __syncthreads();
    const float* wh = g_w + (b*NE + hi)*KK*NM;
    const float* wt = g_w + (b*NE + ti)*KK*NM;
    for (int k = 0; k < KK; k++) {
        float whr[NM], wtr[NM];
        #pragma unroll
        for (int m = 0; m < NM; m++) {
            whr[m] = __ldg(&wh[k*NM + m]);
            wtr[m] = __ldg(&wt[k*NM + m]);
        }
        #pragma unroll
        for (int i2 = 0; i2 < 3; i2++) {
            int d = tid + i2*256;
            float ah = rh[i2], at2 = rt[i2];
            #pragma unroll
            for (int m = 0; m < NM; m++) {
                ah  += whr[m] * sT[m*DD + d];
                at2 += wtr[m] * sT[NM*DD + m*DD + d];
            }
            size_t o = (size_t)(n*KK + k)*DD + d;
            g_hsh[o]  = __float2half_rn(ftanh(ah));
            g_tshi[o] = __float2half_rn(ftanh(at2));
        }
    }
}

// ---------------- K11: bilinear weights -> fp16 ----------------
__global__ void k_bhalf(const float* __restrict__ bil)
{
    size_t i4 = (size_t)blockIdx.x * 256 + threadIdx.x;
    const size_t N4 = (size_t)KK*DD*DD / 4;
    if (i4 >= N4) return;
    float4 v = ((const float4*)bil)[i4];
    __half2* ph = (__half2*)g_Bhi;
    ph[i4*2+0] = __floats2half2_rn(v.x, v.y);
    ph[i4*2+1] = __floats2half2_rn(v.z, v.w);
}

// ================= HMMA (mma.sync fp16) bilinear core, single pass =================
#define SW128(o) ((o) ^ (((o) >> 3) & 0x70))
#define TILE_BYTES 16384                   /* 128 rows x 128B */
#define SH_PITCH 132
#define SMEM_DYN (128*SH_PITCH*4 + 128*2*4 + 1024)

__device__ __forceinline__ void ldm4(uint32_t* r, uint32_t addr)
{
    asm volatile("ldmatrix.sync.aligned.m8n8.x4.shared.b16 {%0,%1,%2,%3}, [%4];"
                 : "=r"(r[0]), "=r"(r[1]), "=r"(r[2]), "=r"(r[3]) : "r"(addr));
}
__device__ __forceinline__ void mma16816(float* c, const uint32_t* a, const uint32_t* b)
{
    asm volatile("mma.sync.aligned.m16n8k16.row.col.f32.f16.f16.f32 "
                 "{%0,%1,%2,%3}, {%4,%5,%6,%7}, {%8,%9}, {%0,%1,%2,%3};"
                 : "+f"(c[0]), "+f"(c[1]), "+f"(c[2]), "+f"(c[3])
                 : "r"(a[0]), "r"(a[1]), "r"(a[2]), "r"(a[3]), "r"(b[0]), "r"(b[1]));
}

__global__ __launch_bounds__(256) void k_bilinear_mma()
{
    extern __shared__ char dsm[];
    char* smem = (char*)((((uintptr_t)dsm) + 1023) & ~(uintptr_t)1023);
    uint32_t sbase = (uint32_t)__cvta_generic_to_shared(smem);

    const int k  = blockIdx.y;
    const int nt = blockIdx.x & 3;
    const int dt = blockIdx.x >> 2;        // 0..5
    const int n0 = nt * 128, d0 = dt * 128;
    const int tid = threadIdx.x;
    const int lane = tid & 31, wid = tid >> 5;
    const int wm = (wid & 3) * 32;
    const int wn = (wid >> 2) * 64;

    const __half* Abase = g_tshi + ((size_t)n0 * KK + k) * DD;
    const __half* Bbase = g_Bhi + ((size_t)k * DD + d0) * DD;

    float acc[2][8][4];
    #pragma unroll
    for (int mi = 0; mi < 2; mi++)
        #pragma unroll
        for (int ni = 0; ni < 8; ni++)
            #pragma unroll
            for (int j = 0; j < 4; j++) acc[mi][ni][j] = 0.f;

    auto fill = [&](int it, int buf) {
        int k0 = it * 64;
        uint32_t abase = sbase + buf*2*TILE_BYTES;
        uint32_t bbase = abase + TILE_BYTES;
        #pragma unroll
        for (int j = 0; j < 8; j++) {
            int c = tid + j*256;
            if (c < 1024) {
                int r = c >> 3, q = c & 7;
                cp16(abase + SW128(r*128 + q*16), Abase + (size_t)r*(KK*DD) + k0 + q*8);
            } else {
                int c2 = c - 1024;
                int r = c2 >> 3, q = c2 & 7;
                cp16(bbase + SW128(r*128 + q*16), Bbase + (size_t)r*DD + k0 + q*8);
            }
        }
    };

    fill(0, 0);
    asm volatile("cp.async.commit_group;");

    for (int i = 0; i < 12; i++) {
        if (i + 1 < 12) {
            fill(i + 1, (i + 1) & 1);
            asm volatile("cp.async.commit_group;");
            asm volatile("cp.async.wait_group 1;");
        } else {
            asm volatile("cp.async.wait_group 0;");
        }
        __syncthreads();

        uint32_t abase = sbase + (i & 1)*2*TILE_BYTES;
        uint32_t bbase = abase + TILE_BYTES;
        #pragma unroll
        for (int ks = 0; ks < 4; ks++) {
            uint32_t af[2][4];
            #pragma unroll
            for (int mi = 0; mi < 2; mi++) {
                int row = wm + mi*16 + ((lane >> 3) & 1)*8 + (lane & 7);
                int cb  = ks*32 + (lane >> 4)*16;
                ldm4(af[mi], abase + SW128(row*128 + cb));
            }
            uint32_t bf[8][2];
            #pragma unroll
            for (int q = 0; q < 4; q++) {
                uint32_t r[4];
                int nrow = wn + (2*q + (lane >> 4))*8 + (lane & 7);
                int cb   = ks*32 + ((lane >> 3) & 1)*16;
                ldm4(r, bbase + SW128(nrow*128 + cb));
                bf[2*q+0][0] = r[0]; bf[2*q+0][1] = r[1];
                bf[2*q+1][0] = r[2]; bf[2*q+1][1] = r[3];
            }
            #pragma unroll
            for (int mi = 0; mi < 2; mi++)
                #pragma unroll
                for (int ni = 0; ni < 8; ni++)
                    mma16816(acc[mi][ni], af[mi], bf[ni]);
        }
        __syncthreads();
    }

    // ---- epilogue: partial[n] = sum_d C[n][d]*hs[n][d] (hs fp16 in gmem) ----
    float* sH  = (float*)smem;
    float* red = (float*)(smem + 128*SH_PITCH*4);
    for (int idx = tid; idx < 128*16; idx += 256) {
        int r = idx >> 4, c8 = idx & 15;
        const __half2* hp = (const __half2*)(g_hsh + ((size_t)(n0 + r)*KK + k)*DD + d0 + c8*8);
        float* dst = &sH[r*SH_PITCH + c8*8];
        #pragma unroll
        for (int u = 0; u < 4; u++) {
            float2 f = __half22float2(hp[u]);
            dst[u*2+0] = f.x; dst[u*2+1] = f.y;
        }
    }
    __syncthreads();

    float p[2][2] = {{0.f, 0.f}, {0.f, 0.f}};
    #pragma unroll
    for (int mi = 0; mi < 2; mi++) {
        int r0 = wm + mi*16 + (lane >> 2);
        #pragma unroll
        for (int ni = 0; ni < 8; ni++) {
            int cb = wn + ni*8 + (lane & 3)*2;
            p[mi][0] += acc[mi][ni][0]*sH[r0*SH_PITCH + cb]
                      + acc[mi][ni][1]*sH[r0*SH_PITCH + cb + 1];
            p[mi][1] += acc[mi][ni][2]*sH[(r0+8)*SH_PITCH + cb]
                      + acc[mi][ni][3]*sH[(r0+8)*SH_PITCH + cb + 1];
        }
    }
    #pragma unroll
    for (int mi = 0; mi < 2; mi++)
        #pragma unroll
        for (int h = 0; h < 2; h++) {
            p[mi][h] += __shfl_xor_sync(0xffffffffu, p[mi][h], 1);
            p[mi][h] += __shfl_xor_sync(0xffffffffu, p[mi][h], 2);
        }
    if ((lane & 3) == 0) {
        int nw = wid >> 2;
        int rr = lane >> 2;
        #pragma unroll
        for (int mi = 0; mi < 2; mi++) {
            red[(wm + mi*16 + rr)*2 + nw]     = p[mi][0];
            red[(wm + mi*16 + rr + 8)*2 + nw] = p[mi][1];
        }
    }
    __syncthreads();
    if (tid < 128)
        g_part[((size_t)dt*NP + n0 + tid)*KK + k] = red[tid*2] + red[tid*2+1];
}

// ---------------- K13: finalize ----------------
__global__ void k_final(const float* __restrict__ bilb, float* __restrict__ out)
{
    int idx = blockIdx.x*256 + threadIdx.x;
    if (idx >= NP*KK) return;
    int k = idx % KK;
    float s = bilb[k];
    #pragma unroll
    for (int t = 0; t < 6; t++) s += g_part[t*(NP*KK) + idx];
    out[idx] = s;
}

// ---------------- launch ----------------
extern "C" void kernel_launch(void* const* d_in, const int* in_sizes, int n_in,
                              void* d_out, int out_size)
{
    const float* seq      = (const float*)d_in[0];
    const float* att      = (const float*)d_in[1];
    const float* mask     = (const float*)d_in[2];
    const int*   mpos     = (const int*)  d_in[3];
    const int*   pairs    = (const int*)  d_in[4];
    const float* Wattn    = (const float*)d_in[5];
    const float* battn    = (const float*)d_in[6];
    const float* attn_net = (const float*)d_in[7];
    const float* Wlin     = (const float*)d_in[8];
    const float* blin     = (const float*)d_in[9];
    const float* Wseg     = (const float*)d_in[10];
    const float* bseg     = (const float*)d_in[11];
    const float* Whead    = (const float*)d_in[12];
    const float* bhead    = (const float*)d_in[13];
    const float* Wtail    = (const float*)d_in[14];
    const float* btail    = (const float*)d_in[15];
    const float* bil      = (const float*)d_in[16];
    const float* bilb     = (const float*)d_in[17];
    float* out = (float*)d_out;

    float *emb, *t1, *htss, *Th, *Tt, *Rh, *Rt;
    cudaGetSymbolAddress((void**)&emb,  g_emb);
    cudaGetSymbolAddress((void**)&t1,   g_t1);
    cudaGetSymbolAddress((void**)&htss, g_htss);
    cudaGetSymbolAddress((void**)&Th,   g_Th);
    cudaGetSymbolAddress((void**)&Tt,   g_Tt);
    cudaGetSymbolAddress((void**)&Rh,   g_Rh);
    cudaGetSymbolAddress((void**)&Rt,   g_Rt);

    cudaFuncSetAttribute(k_bilinear_mma, cudaFuncAttributeMaxDynamicSharedMemorySize, SMEM_DYN);

    // B weight fp16 convert (independent) first
    {
        size_t n4 = (size_t)KK*DD*DD/4;
        k_bhalf<<<(unsigned)((n4 + 255)/256), 256>>>(bil);
    }
    k_antr<<<(RR*128 + 255)/256, 256>>>(attn_net);
    // 1. gather mention embeddings + entity attention rows
    k_gather<<<BBS*NE, 256>>>(seq, att, mask, mpos);
    // 2. t1 = tanh(emb @ Wattn + battn)
    sgemm_ca<<<dim3(RR/64, (BBS*NE*NM)/64), 256>>>(emb, DD, Wattn, RR, battn, t1, RR, DD, 1);
    // 3. fused scores + softmax
    k_scsm<<<BBS*NE, 128>>>(mask);
    // 4/5. T_h / T_t merged
    sgemm_ca_dual<<<dim3(2*(DD/64), (BBS*NE*NM)/64), 256>>>(emb, DD, Whead, Wtail, DD,
                                                            nullptr, nullptr, Th, Tt, DD, DD);
    // 6. S3 = seq @ Wlin
    k_S3<<<BBS*LL, 128>>>(seq, Wlin);
    // 7. ht -> x
    k_htx<<<dim3(NE*NE, BBS), 256>>>(blin);
    // 8. conv + relu at pairs
    k_htss<<<NP, 256>>>(pairs, Wseg, bseg);
    // 9. Rh / Rt merged
    sgemm_ca_dual<<<dim3(2*(DD/64), NP/64), 256>>>(htss, FF, Whead + DD*DD, Wtail + DD*DD, DD,
                                                   bhead, btail, Rh, Rt, DD, FF);
    // 10. hs,ts fp16
    k_hsts<<<NP, 256>>>(pairs);
    // 11. HMMA bilinear: grid (24 tiles, 97 k), fp16 single pass
    k_bilinear_mma<<<dim3(24, 97), 256, SMEM_DYN>>>();
    // 12. finalize
    k_final<<<(NP*KK + 255)/256, 256>>>(bilb, out);
}

// round 8
// speedup vs baseline: 1.6169x; 1.0014x over previous
#include <cuda_runtime.h>
#include <cuda_fp16.h>
#include <math.h>
#include <stdint.h>

#define NE 42
#define NM 8
#define LL 1024
#define DD 768
#define HH 12
#define KK 97
#define FF 256
#define RR 256
#define BBS 4
#define NP 512   /* bs * P */

// ---------------- scratch (device globals; no allocs) ----------------
__device__ float g_emb [BBS*NE*NM*DD];
__device__ float g_as  [BBS*NE*LL*HH];     // TRANSPOSED: [be][l][h]
__device__ float g_t1  [BBS*NE*NM*RR];
__device__ float g_anT [RR*128];           // attn_net transposed, padded 97->128
__device__ float g_w   [BBS*NE*KK*NM];
__device__ float g_Th  [BBS*NE*NM*DD];
__device__ float g_Tt  [BBS*NE*NM*DD];
__device__ float g_S3  [BBS*LL*3];
__device__ float g_x   [BBS*NE*NE*3];
__device__ float g_htss[NP*FF];
__device__ float g_Rh  [NP*DD];
__device__ float g_Rt  [NP*DD];
__device__ __align__(16) __half g_hsh [NP*KK*DD];      // fp16 head reps
__device__ __align__(16) __half g_tshi[NP*KK*DD];      // fp16 tail reps
__device__ __align__(16) __half g_Bhi [KK*DD*DD];      // fp16 bilinear weights
__device__ float g_part[6*NP*KK];

__device__ __forceinline__ float ftanh(float x)
{
    float e = __expf(2.0f * x);
    return 1.0f - 2.0f / (e + 1.0f);
}

__device__ __forceinline__ void cp16(uint32_t dst, const void* src)
{
    asm volatile("cp.async.cg.shared.global [%0], [%1], 16;" :: "r"(dst), "l"(src));
}

// ---------------- K1: fused prep: gather emb+as (transposed) | antr | S3 ----------------
#define GATHER_BLKS (BBS*NE)       /* 168 */
#define ANTR_BLKS   128
#define S3_BLKS     ((BBS*LL)/2)   /* 2048, 2 rows per block */

__global__ __launch_bounds__(256) void k_prep(const float* __restrict__ seq,
                                              const float* __restrict__ att,
                                              const float* __restrict__ mask,
                                              const int* __restrict__ mpos,
                                              const float* __restrict__ attn_net,
                                              const float* __restrict__ Wlin)
{
    int bid = blockIdx.x;
    int tid = threadIdx.x;
    if (bid < GATHER_BLKS) {
        // ---- gather ----
        int be = bid;
        int b  = be / NE;
        __shared__ int   spos[NM];
        __shared__ float smk [NM];
        __shared__ float sinv;
        if (tid < NM) {
            int p = mpos[be*NM + tid] + 1;
            p = max(0, min(p, LL-1));
            spos[tid] = p;
            smk[tid]  = mask[be*NM + tid];
        }
        __syncthreads();
        if (tid == 0) {
            float c = 0.f;
            #pragma unroll
            for (int m = 0; m < NM; m++) c += smk[m];
            sinv = 1.0f / fmaxf(c, 1.0f);
        }
        __syncthreads();
        for (int idx = tid; idx < NM*DD; idx += 256) {
            int m = idx / DD, d = idx - m*DD;
            g_emb[be*NM*DD + idx] = seq[(b*LL + spos[m])*DD + d] * smk[m];
        }
        // entity_as transposed: g_as[be][l][h]
        for (int idx = tid; idx < HH*LL; idx += 256) {
            int h = idx / LL, l = idx - h*LL;
            float acc = 0.f;
            #pragma unroll
            for (int m = 0; m < NM; m++)
                acc += att[((b*HH + h)*LL + spos[m])*LL + l] * smk[m];
            g_as[((size_t)be*LL + l)*HH + h] = acc * sinv;
        }
    } else if (bid < GATHER_BLKS + ANTR_BLKS) {
        // ---- attn_net transpose ----
        int idx = (bid - GATHER_BLKS)*256 + tid;
        int j = idx >> 7, k = idx & 127;
        g_anT[idx] = (k < KK) ? attn_net[k*RR + j] : 0.f;
    } else {
        // ---- S3 = seq @ Wlin, 2 rows per block ----
        int rp = bid - GATHER_BLKS - ANTR_BLKS;
        int half = tid >> 7;
        int t2 = tid & 127;
        int row = rp*2 + half;
        const float* s = seq + (size_t)row*DD;
        float a0 = 0.f, a1 = 0.f, a2 = 0.f;
        for (int j = t2; j < DD; j += 128) {
            float v = s[j];
            a0 += v*Wlin[j*3+0]; a1 += v*Wlin[j*3+1]; a2 += v*Wlin[j*3+2];
        }
        __shared__ float red[2][3][128];
        red[half][0][t2] = a0; red[half][1][t2] = a1; red[half][2][t2] = a2;
        __syncthreads();
        for (int s2 = 64; s2 > 0; s2 >>= 1) {
            if (t2 < s2) {
                red[half][0][t2] += red[half][0][t2+s2];
                red[half][1][t2] += red[half][1][t2+s2];
                red[half][2][t2] += red[half][2][t2+s2];
            }
            __syncthreads();
        }
        if (t2 < 3) g_S3[row*3 + t2] = red[half][t2][0];
    }
}

// ---------------- cp.async double-buffered SGEMM (64x64x32) ----------------
__global__ __launch_bounds__(256) void sgemm_ca(const float* __restrict__ A, int lda,
                                                const float* __restrict__ B, int ldb,
                                                const float* __restrict__ bias,
                                                float* __restrict__ C, int ldc,
                                                int Kd, int act)
{
    __shared__ float As[2][64][32];
    __shared__ float Bs[2][32][68];
    int m0 = blockIdx.y * 64, n0 = blockIdx.x * 64;
    int tid = threadIdx.x;
    int ty = tid >> 4, tx = tid & 15;
    uint32_t sA = (uint32_t)__cvta_generic_to_shared(&As[0][0][0]);
    uint32_t sB = (uint32_t)__cvta_generic_to_shared(&Bs[0][0][0]);
    float acc[4][4];
    #pragma unroll
    for (int i = 0; i < 4; i++)
        #pragma unroll
        for (int j = 0; j < 4; j++) acc[i][j] = 0.f;

    int nstage = Kd >> 5;
    auto fill = [&](int s, int k0) {
        #pragma unroll
        for (int j = 0; j < 2; j++) {
            int c = tid + j*256;
            int r = c >> 3, q = c & 7;
            cp16(sA + (uint32_t)(s*64*32 + r*32 + q*4)*4,
                 A + (size_t)(m0 + r)*lda + k0 + q*4);
            int rb = c >> 4, qb = c & 15;
            cp16(sB + (uint32_t)(s*32*68 + rb*68 + qb*4)*4,
                 B + (size_t)(k0 + rb)*ldb + n0 + qb*4);
        }
        asm volatile("cp.async.commit_group;");
    };

    fill(0, 0);
    for (int s = 0; s < nstage; s++) {
        if (s + 1 < nstage) {
            fill((s + 1) & 1, (s + 1) << 5);
            asm volatile("cp.async.wait_group 1;");
        } else {
            asm volatile("cp.async.wait_group 0;");
        }
        __syncthreads();
        int bs = s & 1;
        #pragma unroll
        for (int kk = 0; kk < 32; kk++) {
            float a[4], bv[4];
            #pragma unroll
            for (int i = 0; i < 4; i++) a[i]  = As[bs][ty*4 + i][kk];
            #pragma unroll
            for (int j = 0; j < 4; j++) bv[j] = Bs[bs][kk][tx*4 + j];
            #pragma unroll
            for (int i = 0; i < 4; i++)
                #pragma unroll
                for (int j = 0; j < 4; j++) acc[i][j] += a[i]*bv[j];
        }
        __syncthreads();
    }
    #pragma unroll
    for (int i = 0; i < 4; i++) {
        int row = m0 + ty*4 + i;
        #pragma unroll
        for (int j = 0; j < 4; j++) {
            int col = n0 + tx*4 + j;
            float v = acc[i][j];
            if (bias) v += bias[col];
            if (act)  v = ftanh(v);
            C[(size_t)row*ldc + col] = v;
        }
    }
}

// ---------------- dual-output cp.async SGEMM ----------------
__global__ __launch_bounds__(256) void sgemm_ca_dual(const float* __restrict__ A, int lda,
                                                     const float* __restrict__ B0,
                                                     const float* __restrict__ B1, int ldb,
                                                     const float* __restrict__ bias0,
                                                     const float* __restrict__ bias1,
                                                     float* __restrict__ C0,
                                                     float* __restrict__ C1, int ldc,
                                                     int Kd)
{
    __shared__ float As[2][64][32];
    __shared__ float Bs[2][32][68];
    int hx = gridDim.x >> 1;
    int half = blockIdx.x >= hx;
    const float* B    = half ? B1    : B0;
    const float* bias = half ? bias1 : bias0;
    float*       C    = half ? C1    : C0;
    int n0 = (blockIdx.x - half*hx) * 64;
    int m0 = blockIdx.y * 64;
    int tid = threadIdx.x;
    int ty = tid >> 4, tx = tid & 15;
    uint32_t sA = (uint32_t)__cvta_generic_to_shared(&As[0][0][0]);
    uint32_t sB = (uint32_t)__cvta_generic_to_shared(&Bs[0][0][0]);
    float acc[4][4];
    #pragma unroll
    for (int i = 0; i < 4; i++)
        #pragma unroll
        for (int j = 0; j < 4; j++) acc[i][j] = 0.f;

    int nstage = Kd >> 5;
    auto fill = [&](int s, int k0) {
        #pragma unroll
        for (int j = 0; j < 2; j++) {
            int c = tid + j*256;
            int r = c >> 3, q = c & 7;
            cp16(sA + (uint32_t)(s*64*32 + r*32 + q*4)*4,
                 A + (size_t)(m0 + r)*lda + k0 + q*4);
            int rb = c >> 4, qb = c & 15;
            cp16(sB + (uint32_t)(s*32*68 + rb*68 + qb*4)*4,
                 B + (size_t)(k0 + rb)*ldb + n0 + qb*4);
        }
        asm volatile("cp.async.commit_group;");
    };

    fill(0, 0);
    for (int s = 0; s < nstage; s++) {
        if (s + 1 < nstage) {
            fill((s + 1) & 1, (s + 1) << 5);
            asm volatile("cp.async.wait_group 1;");
        } else {
            asm volatile("cp.async.wait_group 0;");
        }
        __syncthreads();
        int bs = s & 1;
        #pragma unroll
        for (int kk = 0; kk < 32; kk++) {
            float a[4], bv[4];
            #pragma unroll
            for (int i = 0; i < 4; i++) a[i]  = As[bs][ty*4 + i][kk];
            #pragma unroll
            for (int j = 0; j < 4; j++) bv[j] = Bs[bs][kk][tx*4 + j];
            #pragma unroll
            for (int i = 0; i < 4; i++)
                #pragma unroll
                for (int j = 0; j < 4; j++) acc[i][j] += a[i]*bv[j];
        }
        __syncthreads();
    }
    #pragma unroll
    for (int i = 0; i < 4; i++) {
        int row = m0 + ty*4 + i;
        #pragma unroll
        for (int j = 0; j < 4; j++) {
            int col = n0 + tx*4 + j;
            float v = acc[i][j];
            if (bias) v += bias[col];
            C[(size_t)row*ldc + col] = v;
        }
    }
}

// ---------------- fused scores + softmax over mentions ----------------
__global__ __launch_bounds__(128) void k_scsm(const float* __restrict__ mask)
{
    int be = blockIdx.x;
    int tid = threadIdx.x;
    __shared__ float st[NM*RR];
    for (int i = tid; i < NM*RR/4; i += 128)
        *(float4*)&st[i*4] = *(const float4*)&g_t1[(size_t)be*NM*RR + i*4];
    __syncthreads();
    if (tid >= KK) return;
    float sc[NM];
    #pragma unroll
    for (int m = 0; m < NM; m++)
        sc[m] = (1.0f - mask[be*NM + m]) * (-1e6f);
    for (int j = 0; j < RR; j++) {
        float a = g_anT[j*128 + tid];
        #pragma unroll
        for (int m = 0; m < NM; m++) sc[m] += st[m*RR + j] * a;
    }
    float mx = sc[0];
    #pragma unroll
    for (int m = 1; m < NM; m++) mx = fmaxf(mx, sc[m]);
    float ssum = 0.f;
    #pragma unroll
    for (int m = 0; m < NM; m++) { sc[m] = expf(sc[m] - mx); ssum += sc[m]; }
    float inv = 1.0f / ssum;
    #pragma unroll
    for (int m = 0; m < NM; m++) g_w[(be*KK + tid)*NM + m] = sc[m]*inv;
}

// ---------------- K7: ht + norm + x = ht@S3 + blin; idle blocks convert B->fp16 ----------------
#define BCONV_BLOCKS (861*BBS)                 /* 3444 idle blocks */
#define BCONV_N4     ((size_t)KK*DD*DD/4)      /* 14303232 */
#define BCONV_CHUNK  ((BCONV_N4 + BCONV_BLOCKS - 1)/BCONV_BLOCKS)

__global__ __launch_bounds__(256) void k_htx(const float* __restrict__ blin,
                                             const float* __restrict__ bil)
{
    int b = blockIdx.y;
    int i = blockIdx.x / NE, j = blockIdx.x % NE;
    int tid = threadIdx.x;
    if (j < i) {
        // idle block -> convert a chunk of bilinear weights to fp16
        size_t q = (size_t)b*861 + (size_t)i*(i-1)/2 + j;
        size_t beg = q*BCONV_CHUNK;
        size_t end = beg + BCONV_CHUNK;
        if (end > BCONV_N4) end = BCONV_N4;
        __half2* ph = (__half2*)g_Bhi;
        for (size_t i4 = beg + tid; i4 < end; i4 += 256) {
            float4 v = ((const float4*)bil)[i4];
            ph[i4*2+0] = __floats2half2_rn(v.x, v.y);
            ph[i4*2+1] = __floats2half2_rn(v.z, v.w);
        }
        return;
    }
    const float* ai = g_as + ((size_t)(b*NE + i))*LL*HH;
    const float* aj = g_as + ((size_t)(b*NE + j))*LL*HH;
    const float* s3 = g_S3 + b*LL*3;
    float sum = 0.f, x0 = 0.f, x1 = 0.f, x2 = 0.f;
    for (int l = tid; l < LL; l += 256) {
        float4 u0 = *(const float4*)&ai[l*HH + 0];
        float4 u1 = *(const float4*)&ai[l*HH + 4];
        float4 u2 = *(const float4*)&ai[l*HH + 8];
        float4 v0 = *(const float4*)&aj[l*HH + 0];
        float4 v1 = *(const float4*)&aj[l*HH + 4];
        float4 v2 = *(const float4*)&aj[l*HH + 8];
        float acc = u0.x*v0.x + u0.y*v0.y + u0.z*v0.z + u0.w*v0.w
                  + u1.x*v1.x + u1.y*v1.y + u1.z*v1.z + u1.w*v1.w
                  + u2.x*v2.x + u2.y*v2.y + u2.z*v2.z + u2.w*v2.w;
        acc *= (1.0f / HH);
        sum += acc;
        x0 += acc * s3[l*3+0];
        x1 += acc * s3[l*3+1];
        x2 += acc * s3[l*3+2];
    }
    __shared__ float red[4][256];
    red[0][tid] = sum; red[1][tid] = x0; red[2][tid] = x1; red[3][tid] = x2;
    __syncthreads();
    for (int s2 = 128; s2 > 0; s2 >>= 1) {
        if (tid < s2) {
            red[0][tid] += red[0][tid+s2];
            red[1][tid] += red[1][tid+s2];
            red[2][tid] += red[2][tid+s2];
            red[3][tid] += red[3][tid+s2];
        }
        __syncthreads();
    }
    if (tid == 0) {
        float inv = 1.0f / (red[0][0] + 1e-5f);
        float v0 = red[1][0]*inv + blin[0];
        float v1 = red[2][0]*inv + blin[1];
        float v2 = red[3][0]*inv + blin[2];
        float* xo = g_x + ((b*NE + i)*NE + j)*3;
        xo[0] = v0; xo[1] = v1; xo[2] = v2;
        float* xm = g_x + ((b*NE + j)*NE + i)*3;
        xm[0] = v0; xm[1] = v1; xm[2] = v2;
    }
}

// ---------------- K8: 3x3 conv + relu at pair positions ----------------
__global__ void k_htss(const int* __restrict__ pairs, const float* __restrict__ Wseg,
                       const float* __restrict__ bseg)
{
    int n = blockIdx.x;
    int b = n >> 7;
    int tid = threadIdx.x;
    __shared__ int shi, sti;
    __shared__ float sx[27];
    if (tid == 0) { shi = pairs[n*2]; sti = pairs[n*2+1]; }
    __syncthreads();
    if (tid < 27) {
        int dy = tid / 9, dx = (tid / 3) % 3, c = tid % 3;
        int ii = shi + dy - 1, jj = sti + dx - 1;
        sx[tid] = (ii >= 0 && ii < NE && jj >= 0 && jj < NE)
                  ? g_x[((b*NE + ii)*NE + jj)*3 + c] : 0.f;
    }
    __syncthreads();
    float acc = bseg[tid];
    #pragma unroll
    for (int t = 0; t < 27; t++) acc += sx[t] * Wseg[t*FF + tid];
    g_htss[n*FF + tid] = fmaxf(acc, 0.f);
}

// ---------------- K10: hs,ts -> fp16 ----------------
__global__ __launch_bounds__(256) void k_hsts(const int* __restrict__ pairs)
{
    int n = blockIdx.x;
    int b = n >> 7;
    int tid = threadIdx.x;
    __shared__ float sT[2*NM*DD];
    int hi = pairs[n*2], ti = pairs[n*2+1];
    const float* Th = g_Th + (b*NE + hi)*NM*DD;
    const float* Tt = g_Tt + (b*NE + ti)*NM*DD;
    for (int idx = tid; idx < NM*DD; idx += 256) {
        sT[idx]         = Th[idx];
        sT[NM*DD + idx] = Tt[idx];
    }
    float rh[3], rt[3];
    #pragma unroll
    for (int i2 = 0; i2 < 3; i2++) {
        rh[i2] = g_Rh[n*DD + tid + i2*256];
        rt[i2] = g_Rt[n*DD + tid + i2*256];
    }
    __syncthreads();
    const float* wh = g_w + (b*NE + hi)*KK*NM;
    const float* wt = g_w + (b*NE + ti)*KK*NM;
    for (int k = 0; k < KK; k++) {
        float whr[NM], wtr[NM];
        #pragma unroll
        for (int m = 0; m < NM; m++) {
            whr[m] = __ldg(&wh[k*NM + m]);
            wtr[m] = __ldg(&wt[k*NM + m]);
        }
        #pragma unroll
        for (int i2 = 0; i2 < 3; i2++) {
            int d = tid + i2*256;
            float ah = rh[i2], at2 = rt[i2];
            #pragma unroll
            for (int m = 0; m < NM; m++) {
                ah  += whr[m] * sT[m*DD + d];
                at2 += wtr[m] * sT[NM*DD + m*DD + d];
            }
            size_t o = (size_t)(n*KK + k)*DD + d;
            g_hsh[o]  = __float2half_rn(ftanh(ah));
            g_tshi[o] = __float2half_rn(ftanh(at2));
        }
    }
}

// ================= HMMA (mma.sync fp16) bilinear core, single pass =================
#define SW128(o) ((o) ^ (((o) >> 3) & 0x70))
#define TILE_BYTES 16384
#define SH_PITCH 132
#define SMEM_DYN (128*SH_PITCH*4 + 128*2*4 + 1024)

__device__ __forceinline__ void ldm4(uint32_t* r, uint32_t addr)
{
    asm volatile("ldmatrix.sync.aligned.m8n8.x4.shared.b16 {%0,%1,%2,%3}, [%4];"
                 : "=r"(r[0]), "=r"(r[1]), "=r"(r[2]), "=r"(r[3]) : "r"(addr));
}
__device__ __forceinline__ void mma16816(float* c, const uint32_t* a, const uint32_t* b)
{
    asm volatile("mma.sync.aligned.m16n8k16.row.col.f32.f16.f16.f32 "
                 "{%0,%1,%2,%3}, {%4,%5,%6,%7}, {%8,%9}, {%0,%1,%2,%3};"
                 : "+f"(c[0]), "+f"(c[1]), "+f"(c[2]), "+f"(c[3])
                 : "r"(a[0]), "r"(a[1]), "r"(a[2]), "r"(a[3]), "r"(b[0]), "r"(b[1]));
}

__global__ __launch_bounds__(256) void k_bilinear_mma()
{
    extern __shared__ char dsm[];
    char* smem = (char*)((((uintptr_t)dsm) + 1023) & ~(uintptr_t)1023);
    uint32_t sbase = (uint32_t)__cvta_generic_to_shared(smem);

    const int k  = blockIdx.y;
    const int nt = blockIdx.x & 3;
    const int dt = blockIdx.x >> 2;
    const int n0 = nt * 128, d0 = dt * 128;
    const int tid = threadIdx.x;
    const int lane = tid & 31, wid = tid >> 5;
    const int wm = (wid & 3) * 32;
    const int wn = (wid >> 2) * 64;

    const __half* Abase = g_tshi + ((size_t)n0 * KK + k) * DD;
    const __half* Bbase = g_Bhi + ((size_t)k * DD + d0) * DD;

    float acc[2][8][4];
    #pragma unroll
    for (int mi = 0; mi < 2; mi++)
        #pragma unroll
        for (int ni = 0; ni < 8; ni++)
            #pragma unroll
            for (int j = 0; j < 4; j++) acc[mi][ni][j] = 0.f;

    auto fill = [&](int it, int buf) {
        int k0 = it * 64;
        uint32_t abase = sbase + buf*2*TILE_BYTES;
        uint32_t bbase = abase + TILE_BYTES;
        #pragma unroll
        for (int j = 0; j < 8; j++) {
            int c = tid + j*256;
            if (c < 1024) {
                int r = c >> 3, q = c & 7;
                cp16(abase + SW128(r*128 + q*16), Abase + (size_t)r*(KK*DD) + k0 + q*8);
            } else {
                int c2 = c - 1024;
                int r = c2 >> 3, q = c2 & 7;
                cp16(bbase + SW128(r*128 + q*16), Bbase + (size_t)r*DD + k0 + q*8);
            }
        }
    };

    fill(0, 0);
    asm volatile("cp.async.commit_group;");

    for (int i = 0; i < 12; i++) {
        if (i + 1 < 12) {
            fill(i + 1, (i + 1) & 1);
            asm volatile("cp.async.commit_group;");
            asm volatile("cp.async.wait_group 1;");
        } else {
            asm volatile("cp.async.wait_group 0;");
        }
        __syncthreads();

        uint32_t abase = sbase + (i & 1)*2*TILE_BYTES;
        uint32_t bbase = abase + TILE_BYTES;
        #pragma unroll
        for (int ks = 0; ks < 4; ks++) {
            uint32_t af[2][4];
            #pragma unroll
            for (int mi = 0; mi < 2; mi++) {
                int row = wm + mi*16 + ((lane >> 3) & 1)*8 + (lane & 7);
                int cb  = ks*32 + (lane >> 4)*16;
                ldm4(af[mi], abase + SW128(row*128 + cb));
            }
            uint32_t bf[8][2];
            #pragma unroll
            for (int q = 0; q < 4; q++) {
                uint32_t r[4];
                int nrow = wn + (2*q + (lane >> 4))*8 + (lane & 7);
                int cb   = ks*32 + ((lane >> 3) & 1)*16;
                ldm4(r, bbase + SW128(nrow*128 + cb));
                bf[2*q+0][0] = r[0]; bf[2*q+0][1] = r[1];
                bf[2*q+1][0] = r[2]; bf[2*q+1][1] = r[3];
            }
            #pragma unroll
            for (int mi = 0; mi < 2; mi++)
                #pragma unroll
                for (int ni = 0; ni < 8; ni++)
                    mma16816(acc[mi][ni], af[mi], bf[ni]);
        }
        __syncthreads();
    }

    // ---- epilogue: partial[n] = sum_d C[n][d]*hs[n][d] ----
    float* sH  = (float*)smem;
    float* red = (float*)(smem + 128*SH_PITCH*4);
    for (int idx = tid; idx < 128*16; idx += 256) {
        int r = idx >> 4, c8 = idx & 15;
        const __half2* hp = (const __half2*)(g_hsh + ((size_t)(n0 + r)*KK + k)*DD + d0 + c8*8);
        float* dst = &sH[r*SH_PITCH + c8*8];
        #pragma unroll
        for (int u = 0; u < 4; u++) {
            float2 f = __half22float2(hp[u]);
            dst[u*2+0] = f.x; dst[u*2+1] = f.y;
        }
    }
    __syncthreads();

    float p[2][2] = {{0.f, 0.f}, {0.f, 0.f}};
    #pragma unroll
    for (int mi = 0; mi < 2; mi++) {
        int r0 = wm + mi*16 + (lane >> 2);
        #pragma unroll
        for (int ni = 0; ni < 8; ni++) {
            int cb = wn + ni*8 + (lane & 3)*2;
            p[mi][0] += acc[mi][ni][0]*sH[r0*SH_PITCH + cb]
                      + acc[mi][ni][1]*sH[r0*SH_PITCH + cb + 1];
            p[mi][1] += acc[mi][ni][2]*sH[(r0+8)*SH_PITCH + cb]
                      + acc[mi][ni][3]*sH[(r0+8)*SH_PITCH + cb + 1];
        }
    }
    #pragma unroll
    for (int mi = 0; mi < 2; mi++)
        #pragma unroll
        for (int h = 0; h < 2; h++) {
            p[mi][h] += __shfl_xor_sync(0xffffffffu, p[mi][h], 1);
            p[mi][h] += __shfl_xor_sync(0xffffffffu, p[mi][h], 2);
        }
    if ((lane & 3) == 0) {
        int nw = wid >> 2;
        int rr = lane >> 2;
        #pragma unroll
        for (int mi = 0; mi < 2; mi++) {
            red[(wm + mi*16 + rr)*2 + nw]     = p[mi][0];
            red[(wm + mi*16 + rr + 8)*2 + nw] = p[mi][1];
        }
    }
    __syncthreads();
    if (tid < 128)
        g_part[((size_t)dt*NP + n0 + tid)*KK + k] = red[tid*2] + red[tid*2+1];
}

// ---------------- K13: finalize ----------------
__global__ void k_final(const float* __restrict__ bilb, float* __restrict__ out)
{
    int idx = blockIdx.x*256 + threadIdx.x;
    if (idx >= NP*KK) return;
    int k = idx % KK;
    float s = bilb[k];
    #pragma unroll
    for (int t = 0; t < 6; t++) s += g_part[t*(NP*KK) + idx];
    out[idx] = s;
}

// ---------------- launch ----------------
extern "C" void kernel_launch(void* const* d_in, const int* in_sizes, int n_in,
                              void* d_out, int out_size)
{
    const float* seq      = (const float*)d_in[0];
    const float* att      = (const float*)d_in[1];
    const float* mask     = (const float*)d_in[2];
    const int*   mpos     = (const int*)  d_in[3];
    const int*   pairs    = (const int*)  d_in[4];
    const float* Wattn    = (const float*)d_in[5];
    const float* battn    = (const float*)d_in[6];
    const float* attn_net = (const float*)d_in[7];
    const float* Wlin     = (const float*)d_in[8];
    const float* blin     = (const float*)d_in[9];
    const float* Wseg     = (const float*)d_in[10];
    const float* bseg     = (const float*)d_in[11];
    const float* Whead    = (const float*)d_in[12];
    const float* bhead    = (const float*)d_in[13];
    const float* Wtail    = (const float*)d_in[14];
    const float* btail    = (const float*)d_in[15];
    const float* bil      = (const float*)d_in[16];
    const float* bilb     = (const float*)d_in[17];
    float* out = (float*)d_out;

    float *emb, *t1, *htss, *Th, *Tt, *Rh, *Rt;
    cudaGetSymbolAddress((void**)&emb,  g_emb);
    cudaGetSymbolAddress((void**)&t1,   g_t1);
    cudaGetSymbolAddress((void**)&htss, g_htss);
    cudaGetSymbolAddress((void**)&Th,   g_Th);
    cudaGetSymbolAddress((void**)&Tt,   g_Tt);
    cudaGetSymbolAddress((void**)&Rh,   g_Rh);
    cudaGetSymbolAddress((void**)&Rt,   g_Rt);

    cudaFuncSetAttribute(k_bilinear_mma, cudaFuncAttributeMaxDynamicSharedMemorySize, SMEM_DYN);

    // 1. fused prep: gather | antn transpose | S3
    k_prep<<<GATHER_BLKS + ANTR_BLKS + S3_BLKS, 256>>>(seq, att, mask, mpos, attn_net, Wlin);
    // 2. t1 = tanh(emb @ Wattn + battn)
    sgemm_ca<<<dim3(RR/64, (BBS*NE*NM)/64), 256>>>(emb, DD, Wattn, RR, battn, t1, RR, DD, 1);
    // 3. fused scores + softmax
    k_scsm<<<BBS*NE, 128>>>(mask);
    // 4/5. T_h / T_t merged
    sgemm_ca_dual<<<dim3(2*(DD/64), (BBS*NE*NM)/64), 256>>>(emb, DD, Whead, Wtail, DD,
                                                            nullptr, nullptr, Th, Tt, DD, DD);
    // 6/7. ht -> x  (idle blocks convert bilinear weights to fp16)
    k_htx<<<dim3(NE*NE, BBS), 256>>>(blin, bil);
    // 8. conv + relu at pairs
    k_htss<<<NP, 256>>>(pairs, Wseg, bseg);
    // 9. Rh / Rt merged
    sgemm_ca_dual<<<dim3(2*(DD/64), NP/64), 256>>>(htss, FF, Whead + DD*DD, Wtail + DD*DD, DD,
                                                   bhead, btail, Rh, Rt, DD, FF);
    // 10. hs,ts fp16
    k_hsts<<<NP, 256>>>(pairs);
    // 11. HMMA bilinear: grid (24 tiles, 97 k), fp16 single pass
    k_bilinear_mma<<<dim3(24, 97), 256, SMEM_DYN>>>();
    // 12. finalize
    k_final<<<(NP*KK + 255)/256, 256>>>(bilb, out);
}